// round 1
// baseline (speedup 1.0000x reference)
#include <cuda_runtime.h>

// ---------------------------------------------------------------------------
// ESN_2D: B=256, H=W=32, n=128, alpha^2=25, START_T=1
//  Phase A: wavefront state recurrence (63 diagonal launches)
//  Phase B: per-batch extended Gram (feature dim 258: left|up|1|target)
//  Phase C: per-batch blocked Cholesky solve in shared memory
// ---------------------------------------------------------------------------

#define GSTRIDE 66564  // 258*258

// states: [cell(1024)][b(256)][i(128)]
__device__ float g_S[(size_t)1024 * 256 * 128];
// extended gram, lower triangle filled: [b][i*258+j]
__device__ float g_G[(size_t)256 * GSTRIDE];

// ---- packed f32x2 helpers (Blackwell, 2x FFMA issue rate) ----
__device__ __forceinline__ unsigned long long splat2(float x) {
    unsigned long long r;
    asm("mov.b64 %0, {%1, %1};" : "=l"(r) : "f"(x));
    return r;
}
__device__ __forceinline__ unsigned long long pack2(float lo, float hi) {
    unsigned long long r;
    asm("mov.b64 %0, {%1, %2};" : "=l"(r) : "f"(lo), "f"(hi));
    return r;
}
__device__ __forceinline__ void fma2(unsigned long long &c, unsigned long long a,
                                     unsigned long long b) {
    asm("fma.rn.f32x2 %0, %1, %2, %0;" : "+l"(c) : "l"(a), "l"(b));
}
__device__ __forceinline__ float2 unpk(unsigned long long v) {
    float2 f;
    asm("mov.b64 {%0, %1}, %2;" : "=f"(f.x), "=f"(f.y) : "l"(v));
    return f;
}

// ---------------------------------------------------------------------------
// Phase A: one anti-diagonal step. grid=(cells, 16 batch tiles), block=128.
// Thread t: i-quad ib=t&31 (i = 4*ib..4*ib+3), batch quad bq=t>>5 (4 batches).
// ---------------------------------------------------------------------------
__global__ void __launch_bounds__(128) esn_diag(const float* __restrict__ img,
                                                const float* __restrict__ win,
                                                const float* __restrict__ W1,
                                                const float* __restrict__ W2,
                                                int d)
{
    int hmin = d > 31 ? d - 31 : 0;
    int h = hmin + blockIdx.x;
    int w = d - h;
    int cell = h * 32 + w;
    int b0 = blockIdx.y * 16;
    int t = threadIdx.x;
    int ib = t & 31;
    int bq = t >> 5;

    __shared__ float sL[2048];  // left states [16 b][128]
    __shared__ float sU[2048];  // up states
    {
        float4* dl = (float4*)sL;
        float4* du = (float4*)sU;
        const float4* pl = (w > 0) ? (const float4*)&g_S[(size_t)(cell - 1) * 32768 + b0 * 128]
                                   : (const float4*)0;
        const float4* pu = (h > 0) ? (const float4*)&g_S[(size_t)(cell - 32) * 32768 + b0 * 128]
                                   : (const float4*)0;
        float4 z = make_float4(0.f, 0.f, 0.f, 0.f);
        for (int k = t; k < 512; k += 128) {
            dl[k] = pl ? pl[k] : z;
            du[k] = pu ? pu[k] : z;
        }
    }
    __syncthreads();

    unsigned long long acc[4][2];
#pragma unroll
    for (int bb = 0; bb < 4; ++bb) { acc[bb][0] = 0ull; acc[bb][1] = 0ull; }

    const ulonglong2* W1q = (const ulonglong2*)W1;  // row j as 32 f32x2-pairs-of-pairs
    const ulonglong2* W2q = (const ulonglong2*)W2;
#pragma unroll 4
    for (int j = 0; j < 128; ++j) {
        ulonglong2 w1 = W1q[j * 32 + ib];  // W1[j][4ib..4ib+3]
        ulonglong2 w2 = W2q[j * 32 + ib];
#pragma unroll
        for (int bb = 0; bb < 4; ++bb) {
            unsigned long long l2 = splat2(sL[(bq * 4 + bb) * 128 + j]);
            unsigned long long u2 = splat2(sU[(bq * 4 + bb) * 128 + j]);
            fma2(acc[bb][0], l2, w1.x);
            fma2(acc[bb][1], l2, w1.y);
            fma2(acc[bb][0], u2, w2.x);
            fma2(acc[bb][1], u2, w2.y);
        }
    }

    float4 wv = ((const float4*)win)[ib];
#pragma unroll
    for (int bb = 0; bb < 4; ++bb) {
        int b = b0 + bq * 4 + bb;
        float x = img[b * 1024 + cell];
        float2 a0 = unpk(acc[bb][0]);
        float2 a1 = unpk(acc[bb][1]);
        float4 s;
        s.x = tanhf(fmaf(x, wv.x, a0.x));
        s.y = tanhf(fmaf(x, wv.y, a0.y));
        s.z = tanhf(fmaf(x, wv.z, a1.x));
        s.w = tanhf(fmaf(x, wv.w, a1.y));
        *(float4*)&g_S[(size_t)cell * 32768 + b * 128 + ib * 4] = s;
    }
}

// ---------------------------------------------------------------------------
// Phase B: extended Gram. Feature d: [0,128) left, [128,256) up, 256 -> 1,
// 257 -> target u. Samples s = (h-1)*31 + (w-1), h,w in [1,32).
// ---------------------------------------------------------------------------
__device__ __forceinline__ float fetchF(const float* __restrict__ img, int b, int s, int d)
{
    if (s >= 961 || d > 257) return 0.f;
    if (d == 256) return 1.f;
    int hh = s / 31;          // h-1
    int ww = s - hh * 31;     // w-1
    if (d == 257) return img[b * 1024 + (hh + 1) * 32 + (ww + 1)];
    int cell = (d < 128) ? ((hh + 1) * 32 + ww)   // left neighbor (h, w-1)
                         : (hh * 32 + ww + 1);    // up neighbor   (h-1, w)
    return g_S[(size_t)cell * 32768 + b * 128 + (d & 127)];
}

__device__ const int c_ti[15] = {0,1,1,2,2,2,3,3,3,3,4,4,4,4,4};
__device__ const int c_tj[15] = {0,0,1,0,1,2,0,1,2,3,0,1,2,3,4};

__global__ void __launch_bounds__(256) gram_kernel(const float* __restrict__ img)
{
    int b = blockIdx.y;
    int ti = c_ti[blockIdx.x], tj = c_tj[blockIdx.x];
    int tx = threadIdx.x & 15, ty = threadIdx.x >> 4;

    __shared__ float sA[8][72];
    __shared__ float sB[8][72];

    unsigned long long acc[4][2];
#pragma unroll
    for (int q = 0; q < 4; ++q) { acc[q][0] = 0ull; acc[q][1] = 0ull; }

    for (int c = 0; c < 121; ++c) {  // 121*8 = 968 >= 961 samples
#pragma unroll
        for (int r = 0; r < 2; ++r) {
            int idx = threadIdx.x + r * 256;
            int k = idx >> 6, col = idx & 63;
            int s = c * 8 + k;
            sA[k][col] = fetchF(img, b, s, ti * 64 + col);
            sB[k][col] = fetchF(img, b, s, tj * 64 + col);
        }
        __syncthreads();
#pragma unroll
        for (int k = 0; k < 8; ++k) {
            float4 ra = *(const float4*)&sA[k][ty * 4];
            ulonglong2 rb = *(const ulonglong2*)&sB[k][tx * 4];
            unsigned long long a;
            a = splat2(ra.x); fma2(acc[0][0], a, rb.x); fma2(acc[0][1], a, rb.y);
            a = splat2(ra.y); fma2(acc[1][0], a, rb.x); fma2(acc[1][1], a, rb.y);
            a = splat2(ra.z); fma2(acc[2][0], a, rb.x); fma2(acc[2][1], a, rb.y);
            a = splat2(ra.w); fma2(acc[3][0], a, rb.x); fma2(acc[3][1], a, rb.y);
        }
        __syncthreads();
    }

    size_t gb = (size_t)b * GSTRIDE;
    int j0 = tj * 64 + tx * 4;
#pragma unroll
    for (int ii = 0; ii < 4; ++ii) {
        int i = ti * 64 + ty * 4 + ii;
        if (i >= 258) continue;
        float2 v0 = unpk(acc[ii][0]);
        float2 v1 = unpk(acc[ii][1]);
        float* rowp = &g_G[gb + (size_t)i * 258];
        if (j0     < 258 && j0     <= i) rowp[j0]     = v0.x;
        if (j0 + 1 < 258 && j0 + 1 <= i) rowp[j0 + 1] = v0.y;
        if (j0 + 2 < 258 && j0 + 2 <= i) rowp[j0 + 2] = v1.x;
        if (j0 + 3 < 258 && j0 + 3 <= i) rowp[j0 + 3] = v1.y;
    }
}

// ---------------------------------------------------------------------------
// Phase C: blocked Cholesky (NB=32) + substitutions, packed lower triangle in
// dynamic smem (33153 floats) + rhs (257). One CTA per batch, 256 threads.
// ---------------------------------------------------------------------------
#define TRI(i) ((i) * ((i) + 1) / 2)

__global__ void __launch_bounds__(256) solve_kernel(float* __restrict__ out)
{
    extern __shared__ float sm[];
    float* T = sm;            // packed lower triangle of 257x257
    float* y = sm + 33153;    // rhs / solution
    int b = blockIdx.x;
    int tid = threadIdx.x;
    size_t gb = (size_t)b * GSTRIDE;

    // load A (lower triangle) + alpha^2*I, and rhs = gram row 257
    for (int idx = tid; idx < 33153; idx += 256) {
        int i = (int)((sqrtf(8.f * idx + 1.f) - 1.f) * 0.5f);
        while (TRI(i + 1) <= idx) ++i;
        while (TRI(i) > idx) --i;
        int j = idx - TRI(i);
        float v = g_G[gb + (size_t)i * 258 + j];
        if (i == j) v += 25.f;
        T[idx] = v;
    }
    for (int j = tid; j < 257; j += 256) y[j] = g_G[gb + (size_t)257 * 258 + j];
    __syncthreads();

    for (int kb = 0; kb < 256; kb += 32) {
        // --- 1) factor 32x32 diagonal block (warp 0) ---
        if (tid < 32) {
            for (int c = 0; c < 32; ++c) {
                int crow = TRI(kb + c) + kb;
                float dsq = T[crow + c];
                __syncwarp();
                float dv = sqrtf(dsq);
                if (tid == c) T[crow + c] = dv;
                float lr = 0.f;
                int rrow = TRI(kb + tid) + kb;
                if (tid > c) {
                    lr = T[rrow + c] / dv;
                    T[rrow + c] = lr;
                }
                __syncwarp();
                if (tid > c) {
                    for (int c2 = c + 1; c2 <= tid; ++c2)
                        T[rrow + c2] -= lr * T[TRI(kb + c2) + kb + c];
                }
                __syncwarp();
            }
        }
        __syncthreads();

        // --- 2) panel solve: rows i in [kb+32, 257) ---
        {
            int i = kb + 32 + tid;
            if (i < 257) {
                int ibase = TRI(i) + kb;
                float row[32];
#pragma unroll
                for (int m = 0; m < 32; ++m) row[m] = T[ibase + m];
#pragma unroll
                for (int c = 0; c < 32; ++c) {
                    int lb = TRI(kb + c) + kb;
                    float v = row[c];
#pragma unroll
                    for (int m = 0; m < c; ++m) v -= row[m] * T[lb + m];
                    row[c] = v / T[lb + c];
                }
#pragma unroll
                for (int m = 0; m < 32; ++m) T[ibase + m] = row[m];
            }
        }
        __syncthreads();

        // --- 3) trailing SYRK update: A22 -= L21 L21^T (4x4 reg tiles) ---
        {
            int base = kb + 32;
            int R = 257 - base;
            int Gg = (R + 3) >> 2;
            int nt = Gg * (Gg + 1) / 2;
            for (int tIdx = tid; tIdx < nt; tIdx += 256) {
                int gi = (int)((sqrtf(8.f * tIdx + 1.f) - 1.f) * 0.5f);
                while (TRI(gi + 1) <= tIdx) ++gi;
                while (TRI(gi) > tIdx) --gi;
                int gj = tIdx - TRI(gi);
                int i0 = base + gi * 4, j0 = base + gj * 4;
                int ai[4], aj[4];
#pragma unroll
                for (int q = 0; q < 4; ++q) {
                    int iq = i0 + q; if (iq > 256) iq = 256;
                    int jq = j0 + q; if (jq > 256) jq = 256;
                    ai[q] = TRI(iq) + kb;
                    aj[q] = TRI(jq) + kb;
                }
                unsigned long long acc[4][2];
#pragma unroll
                for (int q = 0; q < 4; ++q) { acc[q][0] = 0ull; acc[q][1] = 0ull; }
#pragma unroll 8
                for (int m = 0; m < 32; ++m) {
                    unsigned long long pb01 = pack2(T[aj[0] + m], T[aj[1] + m]);
                    unsigned long long pb23 = pack2(T[aj[2] + m], T[aj[3] + m]);
#pragma unroll
                    for (int q = 0; q < 4; ++q) {
                        unsigned long long a2 = splat2(T[ai[q] + m]);
                        fma2(acc[q][0], a2, pb01);
                        fma2(acc[q][1], a2, pb23);
                    }
                }
#pragma unroll
                for (int q = 0; q < 4; ++q) {
                    int i = i0 + q;
                    if (i > 256) continue;
                    float2 v0 = unpk(acc[q][0]);
                    float2 v1 = unpk(acc[q][1]);
                    int tb = TRI(i);
                    if (j0     <= i            ) T[tb + j0]     -= v0.x;
                    if (j0 + 1 <= i && j0+1<257) T[tb + j0 + 1] -= v0.y;
                    if (j0 + 2 <= i && j0+2<257) T[tb + j0 + 2] -= v1.x;
                    if (j0 + 3 <= i && j0+3<257) T[tb + j0 + 3] -= v1.y;
                }
            }
        }
        __syncthreads();
    }
    if (tid == 0) T[TRI(256) + 256] = sqrtf(T[TRI(256) + 256]);
    __syncthreads();

    // substitutions in warp 0: L y = rhs, then L^T x = y
    if (tid < 32) {
        for (int k = 0; k < 257; ++k) {
            float num = y[k];
            float dg = T[TRI(k) + k];
            __syncwarp();
            float yk = num / dg;
            if (tid == 0) y[k] = yk;
            for (int i = k + 1 + tid; i < 257; i += 32)
                y[i] -= T[TRI(i) + k] * yk;
            __syncwarp();
        }
        for (int k = 256; k >= 0; --k) {
            float num = y[k];
            float dg = T[TRI(k) + k];
            __syncwarp();
            float xk = num / dg;
            if (tid == 0) y[k] = xk;
            int rb = TRI(k);
            for (int i = tid; i < k; i += 32)
                y[i] -= T[rb + i] * xk;
            __syncwarp();
        }
    }
    __syncthreads();
    for (int j = tid; j < 257; j += 256) out[b * 257 + j] = y[j];
}

// ---------------------------------------------------------------------------
extern "C" void kernel_launch(void* const* d_in, const int* in_sizes, int n_in,
                              void* d_out, int out_size)
{
    (void)in_sizes; (void)n_in; (void)out_size;
    const float* img = (const float*)d_in[0];
    const float* win = (const float*)d_in[1];
    const float* W1  = (const float*)d_in[2];
    const float* W2  = (const float*)d_in[3];
    float* out = (float*)d_out;

    cudaFuncSetAttribute(solve_kernel, cudaFuncAttributeMaxDynamicSharedMemorySize,
                         33410 * (int)sizeof(float));

    for (int d = 0; d < 63; ++d) {
        int hmin = d > 31 ? d - 31 : 0;
        int hmax = d < 31 ? d : 31;
        dim3 grid(hmax - hmin + 1, 16);
        esn_diag<<<grid, 128>>>(img, win, W1, W2, d);
    }
    gram_kernel<<<dim3(15, 256), 256>>>(img);
    solve_kernel<<<256, 256, 33410 * (int)sizeof(float)>>>(out);
}

// round 2
// speedup vs baseline: 1.3913x; 1.3913x over previous
#include <cuda_runtime.h>

// ---------------------------------------------------------------------------
// ESN_2D: B=256, H=W=32, n=128, alpha^2=25, START_T=1
//  Phase A: persistent per-batch-pair wavefront kernel (1 launch, weights in regs)
//  Phase B: per-batch extended Gram (feature dim 258: left|up|1|target)
//  Phase C: per-batch blocked Cholesky solve in shared memory
// ---------------------------------------------------------------------------

#define GSTRIDE 66564  // 258*258

// states: [cell(1024)][b(256)][i(128)]
__device__ float g_S[(size_t)1024 * 256 * 128];
// extended gram, lower triangle filled: [b][i*258+j]
__device__ float g_G[(size_t)256 * GSTRIDE];

// ---- packed f32x2 helpers (Blackwell, 2x FFMA issue rate) ----
__device__ __forceinline__ unsigned long long splat2(float x) {
    unsigned long long r;
    asm("mov.b64 %0, {%1, %1};" : "=l"(r) : "f"(x));
    return r;
}
__device__ __forceinline__ unsigned long long pack2(float lo, float hi) {
    unsigned long long r;
    asm("mov.b64 %0, {%1, %2};" : "=l"(r) : "f"(lo), "f"(hi));
    return r;
}
__device__ __forceinline__ void fma2(unsigned long long &c, unsigned long long a,
                                     unsigned long long b) {
    asm("fma.rn.f32x2 %0, %1, %2, %0;" : "+l"(c) : "l"(a), "l"(b));
}
__device__ __forceinline__ float2 unpk(unsigned long long v) {
    float2 f;
    asm("mov.b64 {%0, %1}, %2;" : "=f"(f.x), "=f"(f.y) : "l"(v));
    return f;
}

// ---------------------------------------------------------------------------
// Phase A: persistent recurrence. grid=128 CTAs (2 batches each), 256 threads.
// Thread t: i-pair ip=t&63 (outputs 2ip, 2ip+1), j-group jg=t>>6 (32 j's).
// Weights held in registers (64 f32x2 each of W1, W2 slices per thread).
// Raster-order cell walk; left/up states in smem; cross-jg reduction in smem.
// ---------------------------------------------------------------------------
__global__ void __launch_bounds__(256) esn_persist(const float* __restrict__ img,
                                                   const float* __restrict__ win,
                                                   const float* __restrict__ W1,
                                                   const float* __restrict__ W2)
{
    int b0 = blockIdx.x * 2;
    int t = threadIdx.x;
    int ip = t & 63;
    int jg = t >> 6;

    // load weight slices into registers: W[j][2ip..2ip+1] for j in [32*jg, 32*jg+32)
    unsigned long long w1r[32], w2r[32];
#pragma unroll
    for (int m = 0; m < 32; ++m) {
        int j = jg * 32 + m;
        w1r[m] = *(const unsigned long long*)&W1[j * 128 + ip * 2];
        w2r[m] = *(const unsigned long long*)&W2[j * 128 + ip * 2];
    }

    __shared__ float rowbuf[2][32][128];  // previous-row states (in-place update)
    __shared__ float lbuf[2][128];        // left-neighbor state
    __shared__ float red[4][2][128];      // per-jg partials

    for (int idx = t; idx < 2 * 32 * 128; idx += 256)
        ((float*)rowbuf)[idx] = 0.f;

    // reduction-thread mapping (t < 128): rp = i-pair, rg = batch-in-pair
    int rp = t & 63;
    int rg = (t >> 6) & 1;
    float2 winp = make_float2(0.f, 0.f);
    if (t < 128) winp = *(const float2*)&win[rp * 2];

    for (int h = 0; h < 32; ++h) {
        if (t < 128) { lbuf[rg][rp * 2] = 0.f; lbuf[rg][rp * 2 + 1] = 0.f; }
        __syncthreads();
        for (int w = 0; w < 32; ++w) {
            int cell = h * 32 + w;
#pragma unroll
            for (int g = 0; g < 2; ++g) {
                unsigned long long accA = 0ull, accB = 0ull;
                const float* lb = &lbuf[g][jg * 32];
                const float* ub = &rowbuf[g][w][jg * 32];
#pragma unroll
                for (int m4 = 0; m4 < 8; ++m4) {
                    float4 lv = *(const float4*)&lb[m4 * 4];
                    float4 uv = *(const float4*)&ub[m4 * 4];
                    fma2(accA, splat2(lv.x), w1r[m4 * 4 + 0]);
                    fma2(accB, splat2(uv.x), w2r[m4 * 4 + 0]);
                    fma2(accA, splat2(lv.y), w1r[m4 * 4 + 1]);
                    fma2(accB, splat2(uv.y), w2r[m4 * 4 + 1]);
                    fma2(accA, splat2(lv.z), w1r[m4 * 4 + 2]);
                    fma2(accB, splat2(uv.z), w2r[m4 * 4 + 2]);
                    fma2(accA, splat2(lv.w), w1r[m4 * 4 + 3]);
                    fma2(accB, splat2(uv.w), w2r[m4 * 4 + 3]);
                }
                float2 a = unpk(accA), bb = unpk(accB);
                *(float2*)&red[jg][g][ip * 2] = make_float2(a.x + bb.x, a.y + bb.y);
            }
            __syncthreads();
            if (t < 128) {
                float2 s0 = *(float2*)&red[0][rg][rp * 2];
                float2 s1 = *(float2*)&red[1][rg][rp * 2];
                float2 s2 = *(float2*)&red[2][rg][rp * 2];
                float2 s3 = *(float2*)&red[3][rg][rp * 2];
                float x = img[(b0 + rg) * 1024 + cell];
                float v0 = tanhf(fmaf(x, winp.x, (s0.x + s1.x) + (s2.x + s3.x)));
                float v1 = tanhf(fmaf(x, winp.y, (s0.y + s1.y) + (s2.y + s3.y)));
                lbuf[rg][rp * 2] = v0;
                lbuf[rg][rp * 2 + 1] = v1;
                rowbuf[rg][w][rp * 2] = v0;
                rowbuf[rg][w][rp * 2 + 1] = v1;
                *(float2*)&g_S[(size_t)cell * 32768 + (size_t)(b0 + rg) * 128 + rp * 2] =
                    make_float2(v0, v1);
            }
            __syncthreads();
        }
    }
}

// ---------------------------------------------------------------------------
// Phase B: extended Gram. Feature d: [0,128) left, [128,256) up, 256 -> 1,
// 257 -> target u. Samples s = (h-1)*31 + (w-1), h,w in [1,32).
// ---------------------------------------------------------------------------
__device__ __forceinline__ float fetchF(const float* __restrict__ img, int b, int s, int d)
{
    if (s >= 961 || d > 257) return 0.f;
    if (d == 256) return 1.f;
    int hh = s / 31;          // h-1
    int ww = s - hh * 31;     // w-1
    if (d == 257) return img[b * 1024 + (hh + 1) * 32 + (ww + 1)];
    int cell = (d < 128) ? ((hh + 1) * 32 + ww)   // left neighbor (h, w-1)
                         : (hh * 32 + ww + 1);    // up neighbor   (h-1, w)
    return g_S[(size_t)cell * 32768 + b * 128 + (d & 127)];
}

__device__ const int c_ti[15] = {0,1,1,2,2,2,3,3,3,3,4,4,4,4,4};
__device__ const int c_tj[15] = {0,0,1,0,1,2,0,1,2,3,0,1,2,3,4};

__global__ void __launch_bounds__(256) gram_kernel(const float* __restrict__ img)
{
    int b = blockIdx.y;
    int ti = c_ti[blockIdx.x], tj = c_tj[blockIdx.x];
    int tx = threadIdx.x & 15, ty = threadIdx.x >> 4;

    __shared__ float sA[8][72];
    __shared__ float sB[8][72];

    unsigned long long acc[4][2];
#pragma unroll
    for (int q = 0; q < 4; ++q) { acc[q][0] = 0ull; acc[q][1] = 0ull; }

    for (int c = 0; c < 121; ++c) {  // 121*8 = 968 >= 961 samples
#pragma unroll
        for (int r = 0; r < 2; ++r) {
            int idx = threadIdx.x + r * 256;
            int k = idx >> 6, col = idx & 63;
            int s = c * 8 + k;
            sA[k][col] = fetchF(img, b, s, ti * 64 + col);
            sB[k][col] = fetchF(img, b, s, tj * 64 + col);
        }
        __syncthreads();
#pragma unroll
        for (int k = 0; k < 8; ++k) {
            float4 ra = *(const float4*)&sA[k][ty * 4];
            ulonglong2 rb = *(const ulonglong2*)&sB[k][tx * 4];
            unsigned long long a;
            a = splat2(ra.x); fma2(acc[0][0], a, rb.x); fma2(acc[0][1], a, rb.y);
            a = splat2(ra.y); fma2(acc[1][0], a, rb.x); fma2(acc[1][1], a, rb.y);
            a = splat2(ra.z); fma2(acc[2][0], a, rb.x); fma2(acc[2][1], a, rb.y);
            a = splat2(ra.w); fma2(acc[3][0], a, rb.x); fma2(acc[3][1], a, rb.y);
        }
        __syncthreads();
    }

    size_t gb = (size_t)b * GSTRIDE;
    int j0 = tj * 64 + tx * 4;
#pragma unroll
    for (int ii = 0; ii < 4; ++ii) {
        int i = ti * 64 + ty * 4 + ii;
        if (i >= 258) continue;
        float2 v0 = unpk(acc[ii][0]);
        float2 v1 = unpk(acc[ii][1]);
        float* rowp = &g_G[gb + (size_t)i * 258];
        if (j0     < 258 && j0     <= i) rowp[j0]     = v0.x;
        if (j0 + 1 < 258 && j0 + 1 <= i) rowp[j0 + 1] = v0.y;
        if (j0 + 2 < 258 && j0 + 2 <= i) rowp[j0 + 2] = v1.x;
        if (j0 + 3 < 258 && j0 + 3 <= i) rowp[j0 + 3] = v1.y;
    }
}

// ---------------------------------------------------------------------------
// Phase C: blocked Cholesky (NB=32) + substitutions, packed lower triangle in
// dynamic smem (33153 floats) + rhs (257). One CTA per batch, 256 threads.
// ---------------------------------------------------------------------------
#define TRI(i) ((i) * ((i) + 1) / 2)

__global__ void __launch_bounds__(256) solve_kernel(float* __restrict__ out)
{
    extern __shared__ float sm[];
    float* T = sm;            // packed lower triangle of 257x257
    float* y = sm + 33153;    // rhs / solution
    int b = blockIdx.x;
    int tid = threadIdx.x;
    size_t gb = (size_t)b * GSTRIDE;

    // load A (lower triangle) + alpha^2*I, and rhs = gram row 257
    for (int idx = tid; idx < 33153; idx += 256) {
        int i = (int)((sqrtf(8.f * idx + 1.f) - 1.f) * 0.5f);
        while (TRI(i + 1) <= idx) ++i;
        while (TRI(i) > idx) --i;
        int j = idx - TRI(i);
        float v = g_G[gb + (size_t)i * 258 + j];
        if (i == j) v += 25.f;
        T[idx] = v;
    }
    for (int j = tid; j < 257; j += 256) y[j] = g_G[gb + (size_t)257 * 258 + j];
    __syncthreads();

    for (int kb = 0; kb < 256; kb += 32) {
        // --- 1) factor 32x32 diagonal block (warp 0) ---
        if (tid < 32) {
            for (int c = 0; c < 32; ++c) {
                int crow = TRI(kb + c) + kb;
                float dsq = T[crow + c];
                __syncwarp();
                float dv = sqrtf(dsq);
                if (tid == c) T[crow + c] = dv;
                float lr = 0.f;
                int rrow = TRI(kb + tid) + kb;
                if (tid > c) {
                    lr = T[rrow + c] / dv;
                    T[rrow + c] = lr;
                }
                __syncwarp();
                if (tid > c) {
                    for (int c2 = c + 1; c2 <= tid; ++c2)
                        T[rrow + c2] -= lr * T[TRI(kb + c2) + kb + c];
                }
                __syncwarp();
            }
        }
        __syncthreads();

        // --- 2) panel solve: rows i in [kb+32, 257) ---
        {
            int i = kb + 32 + tid;
            if (i < 257) {
                int ibase = TRI(i) + kb;
                float row[32];
#pragma unroll
                for (int m = 0; m < 32; ++m) row[m] = T[ibase + m];
#pragma unroll
                for (int c = 0; c < 32; ++c) {
                    int lb = TRI(kb + c) + kb;
                    float v = row[c];
#pragma unroll
                    for (int m = 0; m < c; ++m) v -= row[m] * T[lb + m];
                    row[c] = v / T[lb + c];
                }
#pragma unroll
                for (int m = 0; m < 32; ++m) T[ibase + m] = row[m];
            }
        }
        __syncthreads();

        // --- 3) trailing SYRK update: A22 -= L21 L21^T (4x4 reg tiles) ---
        {
            int base = kb + 32;
            int R = 257 - base;
            int Gg = (R + 3) >> 2;
            int nt = Gg * (Gg + 1) / 2;
            for (int tIdx = tid; tIdx < nt; tIdx += 256) {
                int gi = (int)((sqrtf(8.f * tIdx + 1.f) - 1.f) * 0.5f);
                while (TRI(gi + 1) <= tIdx) ++gi;
                while (TRI(gi) > tIdx) --gi;
                int gj = tIdx - TRI(gi);
                int i0 = base + gi * 4, j0 = base + gj * 4;
                int ai[4], aj[4];
#pragma unroll
                for (int q = 0; q < 4; ++q) {
                    int iq = i0 + q; if (iq > 256) iq = 256;
                    int jq = j0 + q; if (jq > 256) jq = 256;
                    ai[q] = TRI(iq) + kb;
                    aj[q] = TRI(jq) + kb;
                }
                unsigned long long acc[4][2];
#pragma unroll
                for (int q = 0; q < 4; ++q) { acc[q][0] = 0ull; acc[q][1] = 0ull; }
#pragma unroll 8
                for (int m = 0; m < 32; ++m) {
                    unsigned long long pb01 = pack2(T[aj[0] + m], T[aj[1] + m]);
                    unsigned long long pb23 = pack2(T[aj[2] + m], T[aj[3] + m]);
#pragma unroll
                    for (int q = 0; q < 4; ++q) {
                        unsigned long long a2 = splat2(T[ai[q] + m]);
                        fma2(acc[q][0], a2, pb01);
                        fma2(acc[q][1], a2, pb23);
                    }
                }
#pragma unroll
                for (int q = 0; q < 4; ++q) {
                    int i = i0 + q;
                    if (i > 256) continue;
                    float2 v0 = unpk(acc[q][0]);
                    float2 v1 = unpk(acc[q][1]);
                    int tb = TRI(i);
                    if (j0     <= i            ) T[tb + j0]     -= v0.x;
                    if (j0 + 1 <= i && j0+1<257) T[tb + j0 + 1] -= v0.y;
                    if (j0 + 2 <= i && j0+2<257) T[tb + j0 + 2] -= v1.x;
                    if (j0 + 3 <= i && j0+3<257) T[tb + j0 + 3] -= v1.y;
                }
            }
        }
        __syncthreads();
    }
    if (tid == 0) T[TRI(256) + 256] = sqrtf(T[TRI(256) + 256]);
    __syncthreads();

    // substitutions in warp 0: L y = rhs, then L^T x = y
    if (tid < 32) {
        for (int k = 0; k < 257; ++k) {
            float num = y[k];
            float dg = T[TRI(k) + k];
            __syncwarp();
            float yk = num / dg;
            if (tid == 0) y[k] = yk;
            for (int i = k + 1 + tid; i < 257; i += 32)
                y[i] -= T[TRI(i) + k] * yk;
            __syncwarp();
        }
        for (int k = 256; k >= 0; --k) {
            float num = y[k];
            float dg = T[TRI(k) + k];
            __syncwarp();
            float xk = num / dg;
            if (tid == 0) y[k] = xk;
            int rb = TRI(k);
            for (int i = tid; i < k; i += 32)
                y[i] -= T[rb + i] * xk;
            __syncwarp();
        }
    }
    __syncthreads();
    for (int j = tid; j < 257; j += 256) out[b * 257 + j] = y[j];
}

// ---------------------------------------------------------------------------
extern "C" void kernel_launch(void* const* d_in, const int* in_sizes, int n_in,
                              void* d_out, int out_size)
{
    (void)in_sizes; (void)n_in; (void)out_size;
    const float* img = (const float*)d_in[0];
    const float* win = (const float*)d_in[1];
    const float* W1  = (const float*)d_in[2];
    const float* W2  = (const float*)d_in[3];
    float* out = (float*)d_out;

    cudaFuncSetAttribute(solve_kernel, cudaFuncAttributeMaxDynamicSharedMemorySize,
                         33410 * (int)sizeof(float));

    esn_persist<<<128, 256>>>(img, win, W1, W2);
    gram_kernel<<<dim3(15, 256), 256>>>(img);
    solve_kernel<<<256, 256, 33410 * (int)sizeof(float)>>>(out);
}

// round 4
// speedup vs baseline: 1.6531x; 1.1881x over previous
#include <cuda_runtime.h>
#include <cuda_bf16.h>
#include <cstdint>

// ---------------------------------------------------------------------------
// ESN_2D: B=256, H=W=32, n=128, alpha^2=25, START_T=1
//  Phase A: persistent per-batch-pair wavefront kernel (1 launch, weights in regs)
//  Phase B: feat (bf16 hi/lo feature matrix + exact const/target rows)
//           + mma.sync bf16-split Gram (3 accumulated segments, HMMA path)
//  Phase C: per-batch blocked Cholesky solve in shared memory
// ---------------------------------------------------------------------------

#define GSTRIDE 66564  // 258*258

// states: [cell(1024)][b(256)][i(128)]
__device__ float g_S[(size_t)1024 * 256 * 128];
// extended gram, lower triangle filled: [b][i*258+j]; rows 256/257 by feat kernel
__device__ float g_G[(size_t)256 * GSTRIDE];
// bf16 split feature matrices: [b(256)][d(256)][s(1024 padded)]
__device__ unsigned short g_Fhi[(size_t)256 * 256 * 1024];
__device__ unsigned short g_Flo[(size_t)256 * 256 * 1024];

// ---- packed f32x2 helpers ----
__device__ __forceinline__ unsigned long long splat2(float x) {
    unsigned long long r;
    asm("mov.b64 %0, {%1, %1};" : "=l"(r) : "f"(x));
    return r;
}
__device__ __forceinline__ unsigned long long pack2(float lo, float hi) {
    unsigned long long r;
    asm("mov.b64 %0, {%1, %2};" : "=l"(r) : "f"(lo), "f"(hi));
    return r;
}
__device__ __forceinline__ void fma2(unsigned long long &c, unsigned long long a,
                                     unsigned long long b) {
    asm("fma.rn.f32x2 %0, %1, %2, %0;" : "+l"(c) : "l"(a), "l"(b));
}
__device__ __forceinline__ float2 unpk(unsigned long long v) {
    float2 f;
    asm("mov.b64 {%0, %1}, %2;" : "=f"(f.x), "=f"(f.y) : "l"(v));
    return f;
}

// ---- cp.async helpers ----
__device__ __forceinline__ uint32_t smem_u32(const void* p) {
    uint32_t a;
    asm("{ .reg .u64 t; cvta.to.shared.u64 t, %1; cvt.u32.u64 %0, t; }" : "=r"(a) : "l"(p));
    return a;
}
__device__ __forceinline__ void cpasync16(uint32_t dst, const void* src) {
    asm volatile("cp.async.cg.shared.global [%0], [%1], 16;" :: "r"(dst), "l"(src) : "memory");
}
__device__ __forceinline__ void cpasync_commit() {
    asm volatile("cp.async.commit_group;" ::: "memory");
}
__device__ __forceinline__ void cpasync_wait0() {
    asm volatile("cp.async.wait_group 0;" ::: "memory");
}

// ---- bf16 mma.sync (sm_80+, compiles under compute_100) ----
__device__ __forceinline__ void mma16816(float* d, const uint32_t* a, const uint32_t* b) {
    asm volatile(
        "mma.sync.aligned.m16n8k16.row.col.f32.bf16.bf16.f32 "
        "{%0,%1,%2,%3}, {%4,%5,%6,%7}, {%8,%9}, {%0,%1,%2,%3};"
        : "+f"(d[0]), "+f"(d[1]), "+f"(d[2]), "+f"(d[3])
        : "r"(a[0]), "r"(a[1]), "r"(a[2]), "r"(a[3]), "r"(b[0]), "r"(b[1]));
}

// ---------------------------------------------------------------------------
// Phase A: persistent recurrence. grid=128 CTAs (2 batches each), 256 threads.
// ---------------------------------------------------------------------------
__global__ void __launch_bounds__(256) esn_persist(const float* __restrict__ img,
                                                   const float* __restrict__ win,
                                                   const float* __restrict__ W1,
                                                   const float* __restrict__ W2)
{
    int b0 = blockIdx.x * 2;
    int t = threadIdx.x;
    int ip = t & 63;
    int jg = t >> 6;

    unsigned long long w1r[32], w2r[32];
#pragma unroll
    for (int m = 0; m < 32; ++m) {
        int j = jg * 32 + m;
        w1r[m] = *(const unsigned long long*)&W1[j * 128 + ip * 2];
        w2r[m] = *(const unsigned long long*)&W2[j * 128 + ip * 2];
    }

    __shared__ float rowbuf[2][32][128];
    __shared__ float lbuf[2][128];
    __shared__ float red[4][2][128];

    for (int idx = t; idx < 2 * 32 * 128; idx += 256)
        ((float*)rowbuf)[idx] = 0.f;

    int rp = t & 63;
    int rg = (t >> 6) & 1;
    float2 winp = make_float2(0.f, 0.f);
    if (t < 128) winp = *(const float2*)&win[rp * 2];

    for (int h = 0; h < 32; ++h) {
        if (t < 128) { lbuf[rg][rp * 2] = 0.f; lbuf[rg][rp * 2 + 1] = 0.f; }
        __syncthreads();
        for (int w = 0; w < 32; ++w) {
            int cell = h * 32 + w;
#pragma unroll
            for (int g = 0; g < 2; ++g) {
                unsigned long long accA = 0ull, accB = 0ull;
                const float* lb = &lbuf[g][jg * 32];
                const float* ub = &rowbuf[g][w][jg * 32];
#pragma unroll
                for (int m4 = 0; m4 < 8; ++m4) {
                    float4 lv = *(const float4*)&lb[m4 * 4];
                    float4 uv = *(const float4*)&ub[m4 * 4];
                    fma2(accA, splat2(lv.x), w1r[m4 * 4 + 0]);
                    fma2(accB, splat2(uv.x), w2r[m4 * 4 + 0]);
                    fma2(accA, splat2(lv.y), w1r[m4 * 4 + 1]);
                    fma2(accB, splat2(uv.y), w2r[m4 * 4 + 1]);
                    fma2(accA, splat2(lv.z), w1r[m4 * 4 + 2]);
                    fma2(accB, splat2(uv.z), w2r[m4 * 4 + 2]);
                    fma2(accA, splat2(lv.w), w1r[m4 * 4 + 3]);
                    fma2(accB, splat2(uv.w), w2r[m4 * 4 + 3]);
                }
                float2 a = unpk(accA), bb = unpk(accB);
                *(float2*)&red[jg][g][ip * 2] = make_float2(a.x + bb.x, a.y + bb.y);
            }
            __syncthreads();
            if (t < 128) {
                float2 s0 = *(float2*)&red[0][rg][rp * 2];
                float2 s1 = *(float2*)&red[1][rg][rp * 2];
                float2 s2 = *(float2*)&red[2][rg][rp * 2];
                float2 s3 = *(float2*)&red[3][rg][rp * 2];
                float x = img[(b0 + rg) * 1024 + cell];
                float v0 = tanhf(fmaf(x, winp.x, (s0.x + s1.x) + (s2.x + s3.x)));
                float v1 = tanhf(fmaf(x, winp.y, (s0.y + s1.y) + (s2.y + s3.y)));
                lbuf[rg][rp * 2] = v0;
                lbuf[rg][rp * 2 + 1] = v1;
                rowbuf[rg][w][rp * 2] = v0;
                rowbuf[rg][w][rp * 2 + 1] = v1;
                *(float2*)&g_S[(size_t)cell * 32768 + (size_t)(b0 + rg) * 128 + rp * 2] =
                    make_float2(v0, v1);
            }
            __syncthreads();
        }
    }
}

// ---------------------------------------------------------------------------
// feat kernel: builds g_Fhi/g_Flo [b][d][1024] bf16 (s padded with zeros) and
// exact fp32 rows 256 (ones) / 257 (target) of g_G. grid=256 (b), block=256 (d).
// ---------------------------------------------------------------------------
__global__ void __launch_bounds__(256) feat_kernel(const float* __restrict__ img)
{
    int b = blockIdx.x;
    int d = threadIdx.x;
    bool isLeft = d < 128;
    int dd = d & 127;

    float sumF = 0.f, sumUF = 0.f, su = 0.f;
    int hh = 0, ww = 0;

    uint4* outHi = (uint4*)&g_Fhi[((size_t)b * 256 + d) * 1024];
    uint4* outLo = (uint4*)&g_Flo[((size_t)b * 256 + d) * 1024];

    for (int sg = 0; sg < 128; ++sg) {
        unsigned short h8[8], l8[8];
#pragma unroll
        for (int j = 0; j < 8; ++j) {
            int s = sg * 8 + j;
            float f = 0.f, u = 0.f;
            if (s < 961) {
                int cell_l = (hh + 1) * 32 + ww;
                int cell_u = hh * 32 + ww + 1;
                int cell_t = (hh + 1) * 32 + ww + 1;
                int cell = isLeft ? cell_l : cell_u;
                f = g_S[(size_t)cell * 32768 + (size_t)b * 128 + dd];
                u = img[b * 1024 + cell_t];
                ++ww;
                if (ww == 31) { ww = 0; ++hh; }
            }
            __nv_bfloat16 hi = __float2bfloat16_rn(f);
            float hif = __bfloat162float(hi);
            __nv_bfloat16 lo = __float2bfloat16_rn(f - hif);
            h8[j] = __bfloat16_as_ushort(hi);
            l8[j] = __bfloat16_as_ushort(lo);
            sumF += f;
            sumUF += u * f;
            su += u;
        }
        uint4 vh, vl;
        vh.x = (uint32_t)h8[0] | ((uint32_t)h8[1] << 16);
        vh.y = (uint32_t)h8[2] | ((uint32_t)h8[3] << 16);
        vh.z = (uint32_t)h8[4] | ((uint32_t)h8[5] << 16);
        vh.w = (uint32_t)h8[6] | ((uint32_t)h8[7] << 16);
        vl.x = (uint32_t)l8[0] | ((uint32_t)l8[1] << 16);
        vl.y = (uint32_t)l8[2] | ((uint32_t)l8[3] << 16);
        vl.z = (uint32_t)l8[4] | ((uint32_t)l8[5] << 16);
        vl.w = (uint32_t)l8[6] | ((uint32_t)l8[7] << 16);
        outHi[sg] = vh;
        outLo[sg] = vl;
    }

    size_t gb = (size_t)b * GSTRIDE;
    g_G[gb + (size_t)256 * 258 + d] = sumF;
    g_G[gb + (size_t)257 * 258 + d] = sumUF;
    if (d == 0) {
        g_G[gb + (size_t)256 * 258 + 256] = 961.f;
        g_G[gb + (size_t)257 * 258 + 256] = su;
    }
}

// ---------------------------------------------------------------------------
// gram_mma: one CTA per (tile, b), tiles {(0,0),(1,0),(1,1)} of 128x128.
// D = sum_k [hi*hi + lo*hi + hi*lo] over K=1024 (zero-padded).
// 256 threads = 8 warps (2x4). Warp tile 64x32 via m16n8k16 bf16 mma.sync.
// smem: 4 matrices [128][72] bf16 (row stride 72 = conflict-free frag loads).
// ---------------------------------------------------------------------------
#define SROW 72

__global__ void __launch_bounds__(256) gram_mma()
{
    extern __shared__ unsigned short sh[];
    int tile = blockIdx.x;
    int b = blockIdx.y;
    int ti = (tile > 0) ? 1 : 0;
    int tj = (tile == 2) ? 1 : 0;
    bool diag = (ti == tj);

    int tid = threadIdx.x;
    int lane = tid & 31;
    int wq = tid >> 5;
    int warp_m = wq >> 2;   // 0..1
    int warp_n = wq & 3;    // 0..3
    int l4 = lane >> 2;     // group id 0..7
    int lm2 = (lane & 3) * 2;

    unsigned short* Ahi = sh;
    unsigned short* Alo = sh + 128 * SROW;
    unsigned short* Bhi = diag ? Ahi : sh + 2 * 128 * SROW;
    unsigned short* Blo = diag ? Alo : sh + 3 * 128 * SROW;

    uint32_t uAhi = smem_u32(Ahi);
    uint32_t uAlo = smem_u32(Alo);
    uint32_t uBhi = smem_u32(Bhi);
    uint32_t uBlo = smem_u32(Blo);

    const unsigned short* srcAhi = &g_Fhi[((size_t)b * 256 + ti * 128) * 1024];
    const unsigned short* srcAlo = &g_Flo[((size_t)b * 256 + ti * 128) * 1024];
    const unsigned short* srcBhi = &g_Fhi[((size_t)b * 256 + tj * 128) * 1024];
    const unsigned short* srcBlo = &g_Flo[((size_t)b * 256 + tj * 128) * 1024];

    float d[16][4];
#pragma unroll
    for (int q = 0; q < 16; ++q)
#pragma unroll
        for (int r = 0; r < 4; ++r) d[q][r] = 0.f;

    for (int c = 0; c < 16; ++c) {
        int s0 = c * 64;
        // load chunk: each matrix = 128 rows x 8 x 16B; 256 threads -> 4 each
#pragma unroll
        for (int q = 0; q < 4; ++q) {
            int idx = tid + q * 256;
            int r = idx >> 3, cc = idx & 7;
            uint32_t dsto = (uint32_t)(r * SROW * 2 + cc * 16);
            size_t srco = (size_t)r * 1024 + s0 + cc * 8;
            cpasync16(uAhi + dsto, srcAhi + srco);
            cpasync16(uAlo + dsto, srcAlo + srco);
            if (!diag) {
                cpasync16(uBhi + dsto, srcBhi + srco);
                cpasync16(uBlo + dsto, srcBlo + srco);
            }
        }
        cpasync_commit();
        cpasync_wait0();
        __syncthreads();

#pragma unroll
        for (int ks = 0; ks < 4; ++ks) {
            int k0 = ks * 16;
            uint32_t aH[4][4], aL[4][4], bH[4][2], bL[4][2];
#pragma unroll
            for (int mt = 0; mt < 4; ++mt) {
                int r0 = warp_m * 64 + mt * 16 + l4;
                const unsigned short* p0 = &Ahi[r0 * SROW + k0 + lm2];
                const unsigned short* p1 = &Ahi[(r0 + 8) * SROW + k0 + lm2];
                aH[mt][0] = *(const uint32_t*)p0;
                aH[mt][1] = *(const uint32_t*)p1;
                aH[mt][2] = *(const uint32_t*)(p0 + 8);
                aH[mt][3] = *(const uint32_t*)(p1 + 8);
                const unsigned short* q0 = &Alo[r0 * SROW + k0 + lm2];
                const unsigned short* q1 = &Alo[(r0 + 8) * SROW + k0 + lm2];
                aL[mt][0] = *(const uint32_t*)q0;
                aL[mt][1] = *(const uint32_t*)q1;
                aL[mt][2] = *(const uint32_t*)(q0 + 8);
                aL[mt][3] = *(const uint32_t*)(q1 + 8);
            }
#pragma unroll
            for (int nt = 0; nt < 4; ++nt) {
                int n0 = warp_n * 32 + nt * 8 + l4;
                const unsigned short* p = &Bhi[n0 * SROW + k0 + lm2];
                bH[nt][0] = *(const uint32_t*)p;
                bH[nt][1] = *(const uint32_t*)(p + 8);
                const unsigned short* q = &Blo[n0 * SROW + k0 + lm2];
                bL[nt][0] = *(const uint32_t*)q;
                bL[nt][1] = *(const uint32_t*)(q + 8);
            }
#pragma unroll
            for (int mt = 0; mt < 4; ++mt)
#pragma unroll
                for (int nt = 0; nt < 4; ++nt) {
                    mma16816(d[mt * 4 + nt], aH[mt], bH[nt]);
                    mma16816(d[mt * 4 + nt], aL[mt], bH[nt]);
                    mma16816(d[mt * 4 + nt], aH[mt], bL[nt]);
                }
        }
        __syncthreads();
    }

    // epilogue: write 128x128 tile into g_G
    size_t gb = (size_t)b * GSTRIDE;
#pragma unroll
    for (int mt = 0; mt < 4; ++mt) {
#pragma unroll
        for (int nt = 0; nt < 4; ++nt) {
            int i0 = ti * 128 + warp_m * 64 + mt * 16 + l4;
            int j0 = tj * 128 + warp_n * 32 + nt * 8 + lm2;
            float* dst0 = &g_G[gb + (size_t)i0 * 258 + j0];
            float* dst1 = &g_G[gb + (size_t)(i0 + 8) * 258 + j0];
            *(float2*)dst0 = make_float2(d[mt * 4 + nt][0], d[mt * 4 + nt][1]);
            *(float2*)dst1 = make_float2(d[mt * 4 + nt][2], d[mt * 4 + nt][3]);
        }
    }
}

// ---------------------------------------------------------------------------
// Phase C: blocked Cholesky (NB=32) + substitutions. One CTA per batch.
// ---------------------------------------------------------------------------
#define TRI(i) ((i) * ((i) + 1) / 2)

__global__ void __launch_bounds__(256) solve_kernel(float* __restrict__ out)
{
    extern __shared__ float sm[];
    float* T = sm;
    float* y = sm + 33153;
    int b = blockIdx.x;
    int tid = threadIdx.x;
    size_t gb = (size_t)b * GSTRIDE;

    for (int idx = tid; idx < 33153; idx += 256) {
        int i = (int)((sqrtf(8.f * idx + 1.f) - 1.f) * 0.5f);
        while (TRI(i + 1) <= idx) ++i;
        while (TRI(i) > idx) --i;
        int j = idx - TRI(i);
        float v = g_G[gb + (size_t)i * 258 + j];
        if (i == j) v += 25.f;
        T[idx] = v;
    }
    for (int j = tid; j < 257; j += 256) y[j] = g_G[gb + (size_t)257 * 258 + j];
    __syncthreads();

    for (int kb = 0; kb < 256; kb += 32) {
        if (tid < 32) {
            for (int c = 0; c < 32; ++c) {
                int crow = TRI(kb + c) + kb;
                float dsq = T[crow + c];
                __syncwarp();
                float dv = sqrtf(dsq);
                if (tid == c) T[crow + c] = dv;
                float lr = 0.f;
                int rrow = TRI(kb + tid) + kb;
                if (tid > c) {
                    lr = T[rrow + c] / dv;
                    T[rrow + c] = lr;
                }
                __syncwarp();
                if (tid > c) {
                    for (int c2 = c + 1; c2 <= tid; ++c2)
                        T[rrow + c2] -= lr * T[TRI(kb + c2) + kb + c];
                }
                __syncwarp();
            }
        }
        __syncthreads();

        {
            int i = kb + 32 + tid;
            if (i < 257) {
                int ibase = TRI(i) + kb;
                float row[32];
#pragma unroll
                for (int m = 0; m < 32; ++m) row[m] = T[ibase + m];
#pragma unroll
                for (int c = 0; c < 32; ++c) {
                    int lb = TRI(kb + c) + kb;
                    float v = row[c];
#pragma unroll
                    for (int m = 0; m < c; ++m) v -= row[m] * T[lb + m];
                    row[c] = v / T[lb + c];
                }
#pragma unroll
                for (int m = 0; m < 32; ++m) T[ibase + m] = row[m];
            }
        }
        __syncthreads();

        {
            int base = kb + 32;
            int R = 257 - base;
            int Gg = (R + 3) >> 2;
            int nt = Gg * (Gg + 1) / 2;
            for (int tIdx = tid; tIdx < nt; tIdx += 256) {
                int gi = (int)((sqrtf(8.f * tIdx + 1.f) - 1.f) * 0.5f);
                while (TRI(gi + 1) <= tIdx) ++gi;
                while (TRI(gi) > tIdx) --gi;
                int gj = tIdx - TRI(gi);
                int i0 = base + gi * 4, j0 = base + gj * 4;
                int ai[4], aj[4];
#pragma unroll
                for (int q = 0; q < 4; ++q) {
                    int iq = i0 + q; if (iq > 256) iq = 256;
                    int jq = j0 + q; if (jq > 256) jq = 256;
                    ai[q] = TRI(iq) + kb;
                    aj[q] = TRI(jq) + kb;
                }
                unsigned long long acc[4][2];
#pragma unroll
                for (int q = 0; q < 4; ++q) { acc[q][0] = 0ull; acc[q][1] = 0ull; }
#pragma unroll 8
                for (int m = 0; m < 32; ++m) {
                    unsigned long long pb01 = pack2(T[aj[0] + m], T[aj[1] + m]);
                    unsigned long long pb23 = pack2(T[aj[2] + m], T[aj[3] + m]);
#pragma unroll
                    for (int q = 0; q < 4; ++q) {
                        unsigned long long a2 = splat2(T[ai[q] + m]);
                        fma2(acc[q][0], a2, pb01);
                        fma2(acc[q][1], a2, pb23);
                    }
                }
#pragma unroll
                for (int q = 0; q < 4; ++q) {
                    int i = i0 + q;
                    if (i > 256) continue;
                    float2 v0 = unpk(acc[q][0]);
                    float2 v1 = unpk(acc[q][1]);
                    int tb = TRI(i);
                    if (j0     <= i            ) T[tb + j0]     -= v0.x;
                    if (j0 + 1 <= i && j0+1<257) T[tb + j0 + 1] -= v0.y;
                    if (j0 + 2 <= i && j0+2<257) T[tb + j0 + 2] -= v1.x;
                    if (j0 + 3 <= i && j0+3<257) T[tb + j0 + 3] -= v1.y;
                }
            }
        }
        __syncthreads();
    }
    if (tid == 0) T[TRI(256) + 256] = sqrtf(T[TRI(256) + 256]);
    __syncthreads();

    if (tid < 32) {
        for (int k = 0; k < 257; ++k) {
            float num = y[k];
            float dg = T[TRI(k) + k];
            __syncwarp();
            float yk = num / dg;
            if (tid == 0) y[k] = yk;
            for (int i = k + 1 + tid; i < 257; i += 32)
                y[i] -= T[TRI(i) + k] * yk;
            __syncwarp();
        }
        for (int k = 256; k >= 0; --k) {
            float num = y[k];
            float dg = T[TRI(k) + k];
            __syncwarp();
            float xk = num / dg;
            if (tid == 0) y[k] = xk;
            int rb = TRI(k);
            for (int i = tid; i < k; i += 32)
                y[i] -= T[rb + i] * xk;
            __syncwarp();
        }
    }
    __syncthreads();
    for (int j = tid; j < 257; j += 256) out[b * 257 + j] = y[j];
}

// ---------------------------------------------------------------------------
extern "C" void kernel_launch(void* const* d_in, const int* in_sizes, int n_in,
                              void* d_out, int out_size)
{
    (void)in_sizes; (void)n_in; (void)out_size;
    const float* img = (const float*)d_in[0];
    const float* win = (const float*)d_in[1];
    const float* W1  = (const float*)d_in[2];
    const float* W2  = (const float*)d_in[3];
    float* out = (float*)d_out;

    cudaFuncSetAttribute(solve_kernel, cudaFuncAttributeMaxDynamicSharedMemorySize,
                         33410 * (int)sizeof(float));
    int gram_smem = 4 * 128 * SROW * 2;  // 73728 bytes
    cudaFuncSetAttribute(gram_mma, cudaFuncAttributeMaxDynamicSharedMemorySize, gram_smem);

    esn_persist<<<128, 256>>>(img, win, W1, W2);
    feat_kernel<<<256, 256>>>(img);
    gram_mma<<<dim3(3, 256), 256, gram_smem>>>();
    solve_kernel<<<256, 256, 33410 * (int)sizeof(float)>>>(out);
}

// round 5
// speedup vs baseline: 1.6658x; 1.0077x over previous
#include <cuda_runtime.h>
#include <cuda_bf16.h>
#include <cstdint>

// ---------------------------------------------------------------------------
// ESN_2D: B=256, H=W=32, n=128, alpha^2=25, START_T=1
//  Phase A: persistent per-batch-pair wavefront kernel (1 launch, weights in regs)
//  Phase B: feat (bf16 hi/lo feature matrix + exact const/target rows)
//           + mma.sync bf16-split Gram (3 accumulated segments, HMMA path)
//  Phase C: per-batch blocked Cholesky solve, panel staged conflict-free
// ---------------------------------------------------------------------------

#define GSTRIDE 66564  // 258*258

// states: [cell(1024)][b(256)][i(128)]
__device__ float g_S[(size_t)1024 * 256 * 128];
// extended gram, lower triangle filled: [b][i*258+j]; rows 256/257 by feat kernel
__device__ float g_G[(size_t)256 * GSTRIDE];
// bf16 split feature matrices: [b(256)][d(256)][s(1024 padded)]
__device__ unsigned short g_Fhi[(size_t)256 * 256 * 1024];
__device__ unsigned short g_Flo[(size_t)256 * 256 * 1024];

// ---- packed f32x2 helpers ----
__device__ __forceinline__ unsigned long long splat2(float x) {
    unsigned long long r;
    asm("mov.b64 %0, {%1, %1};" : "=l"(r) : "f"(x));
    return r;
}
__device__ __forceinline__ unsigned long long pack2(float lo, float hi) {
    unsigned long long r;
    asm("mov.b64 %0, {%1, %2};" : "=l"(r) : "f"(lo), "f"(hi));
    return r;
}
__device__ __forceinline__ void fma2(unsigned long long &c, unsigned long long a,
                                     unsigned long long b) {
    asm("fma.rn.f32x2 %0, %1, %2, %0;" : "+l"(c) : "l"(a), "l"(b));
}
__device__ __forceinline__ float2 unpk(unsigned long long v) {
    float2 f;
    asm("mov.b64 {%0, %1}, %2;" : "=f"(f.x), "=f"(f.y) : "l"(v));
    return f;
}

// ---- cp.async helpers ----
__device__ __forceinline__ uint32_t smem_u32(const void* p) {
    uint32_t a;
    asm("{ .reg .u64 t; cvta.to.shared.u64 t, %1; cvt.u32.u64 %0, t; }" : "=r"(a) : "l"(p));
    return a;
}
__device__ __forceinline__ void cpasync16(uint32_t dst, const void* src) {
    asm volatile("cp.async.cg.shared.global [%0], [%1], 16;" :: "r"(dst), "l"(src) : "memory");
}
__device__ __forceinline__ void cpasync_commit() {
    asm volatile("cp.async.commit_group;" ::: "memory");
}
__device__ __forceinline__ void cpasync_wait0() {
    asm volatile("cp.async.wait_group 0;" ::: "memory");
}

// ---- bf16 mma.sync (sm_80+, compiles under compute_100) ----
__device__ __forceinline__ void mma16816(float* d, const uint32_t* a, const uint32_t* b) {
    asm volatile(
        "mma.sync.aligned.m16n8k16.row.col.f32.bf16.bf16.f32 "
        "{%0,%1,%2,%3}, {%4,%5,%6,%7}, {%8,%9}, {%0,%1,%2,%3};"
        : "+f"(d[0]), "+f"(d[1]), "+f"(d[2]), "+f"(d[3])
        : "r"(a[0]), "r"(a[1]), "r"(a[2]), "r"(a[3]), "r"(b[0]), "r"(b[1]));
}

// ---------------------------------------------------------------------------
// Phase A: persistent recurrence. grid=128 CTAs (2 batches each), 256 threads.
// Reduce/tanh tail spread across all 256 threads (1 output each).
// ---------------------------------------------------------------------------
__global__ void __launch_bounds__(256) esn_persist(const float* __restrict__ img,
                                                   const float* __restrict__ win,
                                                   const float* __restrict__ W1,
                                                   const float* __restrict__ W2)
{
    int b0 = blockIdx.x * 2;
    int t = threadIdx.x;
    int ip = t & 63;
    int jg = t >> 6;

    unsigned long long w1r[32], w2r[32];
#pragma unroll
    for (int m = 0; m < 32; ++m) {
        int j = jg * 32 + m;
        w1r[m] = *(const unsigned long long*)&W1[j * 128 + ip * 2];
        w2r[m] = *(const unsigned long long*)&W2[j * 128 + ip * 2];
    }

    __shared__ float rowbuf[2][32][128];
    __shared__ float lbuf[2][128];
    __shared__ float red[4][2][128];

    for (int idx = t; idx < 2 * 32 * 128; idx += 256)
        ((float*)rowbuf)[idx] = 0.f;

    // reduce mapping: 1 output per thread
    int rg = t >> 7;       // batch in pair
    int ri = t & 127;      // state index
    float winv = win[ri];

    for (int h = 0; h < 32; ++h) {
        lbuf[rg][ri] = 0.f;
        __syncthreads();
        for (int w = 0; w < 32; ++w) {
            int cell = h * 32 + w;
#pragma unroll
            for (int g = 0; g < 2; ++g) {
                unsigned long long accA = 0ull, accB = 0ull;
                const float* lb = &lbuf[g][jg * 32];
                const float* ub = &rowbuf[g][w][jg * 32];
#pragma unroll
                for (int m4 = 0; m4 < 8; ++m4) {
                    float4 lv = *(const float4*)&lb[m4 * 4];
                    float4 uv = *(const float4*)&ub[m4 * 4];
                    fma2(accA, splat2(lv.x), w1r[m4 * 4 + 0]);
                    fma2(accB, splat2(uv.x), w2r[m4 * 4 + 0]);
                    fma2(accA, splat2(lv.y), w1r[m4 * 4 + 1]);
                    fma2(accB, splat2(uv.y), w2r[m4 * 4 + 1]);
                    fma2(accA, splat2(lv.z), w1r[m4 * 4 + 2]);
                    fma2(accB, splat2(uv.z), w2r[m4 * 4 + 2]);
                    fma2(accA, splat2(lv.w), w1r[m4 * 4 + 3]);
                    fma2(accB, splat2(uv.w), w2r[m4 * 4 + 3]);
                }
                float2 a = unpk(accA), bb = unpk(accB);
                *(float2*)&red[jg][g][ip * 2] = make_float2(a.x + bb.x, a.y + bb.y);
            }
            __syncthreads();
            {
                float s = (red[0][rg][ri] + red[1][rg][ri]) +
                          (red[2][rg][ri] + red[3][rg][ri]);
                float x = img[(b0 + rg) * 1024 + cell];
                float v = tanhf(fmaf(x, winv, s));
                lbuf[rg][ri] = v;
                rowbuf[rg][w][ri] = v;
                g_S[(size_t)cell * 32768 + (size_t)(b0 + rg) * 128 + ri] = v;
            }
            __syncthreads();
        }
    }
}

// ---------------------------------------------------------------------------
// feat kernel: builds g_Fhi/g_Flo [b][d][1024] bf16 (s padded with zeros) and
// exact fp32 rows 256 (ones) / 257 (target) of g_G. grid=256 (b), block=256 (d).
// ---------------------------------------------------------------------------
__global__ void __launch_bounds__(256) feat_kernel(const float* __restrict__ img)
{
    int b = blockIdx.x;
    int d = threadIdx.x;
    bool isLeft = d < 128;
    int dd = d & 127;

    float sumF = 0.f, sumUF = 0.f, su = 0.f;
    int hh = 0, ww = 0;

    uint4* outHi = (uint4*)&g_Fhi[((size_t)b * 256 + d) * 1024];
    uint4* outLo = (uint4*)&g_Flo[((size_t)b * 256 + d) * 1024];

    for (int sg = 0; sg < 128; ++sg) {
        unsigned short h8[8], l8[8];
#pragma unroll
        for (int j = 0; j < 8; ++j) {
            int s = sg * 8 + j;
            float f = 0.f, u = 0.f;
            if (s < 961) {
                int cell_l = (hh + 1) * 32 + ww;
                int cell_u = hh * 32 + ww + 1;
                int cell_t = (hh + 1) * 32 + ww + 1;
                int cell = isLeft ? cell_l : cell_u;
                f = g_S[(size_t)cell * 32768 + (size_t)b * 128 + dd];
                u = img[b * 1024 + cell_t];
                ++ww;
                if (ww == 31) { ww = 0; ++hh; }
            }
            __nv_bfloat16 hi = __float2bfloat16_rn(f);
            float hif = __bfloat162float(hi);
            __nv_bfloat16 lo = __float2bfloat16_rn(f - hif);
            h8[j] = __bfloat16_as_ushort(hi);
            l8[j] = __bfloat16_as_ushort(lo);
            sumF += f;
            sumUF += u * f;
            su += u;
        }
        uint4 vh, vl;
        vh.x = (uint32_t)h8[0] | ((uint32_t)h8[1] << 16);
        vh.y = (uint32_t)h8[2] | ((uint32_t)h8[3] << 16);
        vh.z = (uint32_t)h8[4] | ((uint32_t)h8[5] << 16);
        vh.w = (uint32_t)h8[6] | ((uint32_t)h8[7] << 16);
        vl.x = (uint32_t)l8[0] | ((uint32_t)l8[1] << 16);
        vl.y = (uint32_t)l8[2] | ((uint32_t)l8[3] << 16);
        vl.z = (uint32_t)l8[4] | ((uint32_t)l8[5] << 16);
        vl.w = (uint32_t)l8[6] | ((uint32_t)l8[7] << 16);
        outHi[sg] = vh;
        outLo[sg] = vl;
    }

    size_t gb = (size_t)b * GSTRIDE;
    g_G[gb + (size_t)256 * 258 + d] = sumF;
    g_G[gb + (size_t)257 * 258 + d] = sumUF;
    if (d == 0) {
        g_G[gb + (size_t)256 * 258 + 256] = 961.f;
        g_G[gb + (size_t)257 * 258 + 256] = su;
    }
}

// ---------------------------------------------------------------------------
// gram_mma: one CTA per (tile, b), tiles {(0,0),(1,0),(1,1)} of 128x128.
// ---------------------------------------------------------------------------
#define SROW 72

__global__ void __launch_bounds__(256) gram_mma()
{
    extern __shared__ unsigned short sh[];
    int tile = blockIdx.x;
    int b = blockIdx.y;
    int ti = (tile > 0) ? 1 : 0;
    int tj = (tile == 2) ? 1 : 0;
    bool diag = (ti == tj);

    int tid = threadIdx.x;
    int lane = tid & 31;
    int wq = tid >> 5;
    int warp_m = wq >> 2;   // 0..1
    int warp_n = wq & 3;    // 0..3
    int l4 = lane >> 2;     // group id 0..7
    int lm2 = (lane & 3) * 2;

    unsigned short* Ahi = sh;
    unsigned short* Alo = sh + 128 * SROW;
    unsigned short* Bhi = diag ? Ahi : sh + 2 * 128 * SROW;
    unsigned short* Blo = diag ? Alo : sh + 3 * 128 * SROW;

    uint32_t uAhi = smem_u32(Ahi);
    uint32_t uAlo = smem_u32(Alo);
    uint32_t uBhi = smem_u32(Bhi);
    uint32_t uBlo = smem_u32(Blo);

    const unsigned short* srcAhi = &g_Fhi[((size_t)b * 256 + ti * 128) * 1024];
    const unsigned short* srcAlo = &g_Flo[((size_t)b * 256 + ti * 128) * 1024];
    const unsigned short* srcBhi = &g_Fhi[((size_t)b * 256 + tj * 128) * 1024];
    const unsigned short* srcBlo = &g_Flo[((size_t)b * 256 + tj * 128) * 1024];

    float d[16][4];
#pragma unroll
    for (int q = 0; q < 16; ++q)
#pragma unroll
        for (int r = 0; r < 4; ++r) d[q][r] = 0.f;

    for (int c = 0; c < 16; ++c) {
        int s0 = c * 64;
#pragma unroll
        for (int q = 0; q < 4; ++q) {
            int idx = tid + q * 256;
            int r = idx >> 3, cc = idx & 7;
            uint32_t dsto = (uint32_t)(r * SROW * 2 + cc * 16);
            size_t srco = (size_t)r * 1024 + s0 + cc * 8;
            cpasync16(uAhi + dsto, srcAhi + srco);
            cpasync16(uAlo + dsto, srcAlo + srco);
            if (!diag) {
                cpasync16(uBhi + dsto, srcBhi + srco);
                cpasync16(uBlo + dsto, srcBlo + srco);
            }
        }
        cpasync_commit();
        cpasync_wait0();
        __syncthreads();

#pragma unroll
        for (int ks = 0; ks < 4; ++ks) {
            int k0 = ks * 16;
            uint32_t aH[4][4], aL[4][4], bH[4][2], bL[4][2];
#pragma unroll
            for (int mt = 0; mt < 4; ++mt) {
                int r0 = warp_m * 64 + mt * 16 + l4;
                const unsigned short* p0 = &Ahi[r0 * SROW + k0 + lm2];
                const unsigned short* p1 = &Ahi[(r0 + 8) * SROW + k0 + lm2];
                aH[mt][0] = *(const uint32_t*)p0;
                aH[mt][1] = *(const uint32_t*)p1;
                aH[mt][2] = *(const uint32_t*)(p0 + 8);
                aH[mt][3] = *(const uint32_t*)(p1 + 8);
                const unsigned short* q0 = &Alo[r0 * SROW + k0 + lm2];
                const unsigned short* q1 = &Alo[(r0 + 8) * SROW + k0 + lm2];
                aL[mt][0] = *(const uint32_t*)q0;
                aL[mt][1] = *(const uint32_t*)q1;
                aL[mt][2] = *(const uint32_t*)(q0 + 8);
                aL[mt][3] = *(const uint32_t*)(q1 + 8);
            }
#pragma unroll
            for (int nt = 0; nt < 4; ++nt) {
                int n0 = warp_n * 32 + nt * 8 + l4;
                const unsigned short* p = &Bhi[n0 * SROW + k0 + lm2];
                bH[nt][0] = *(const uint32_t*)p;
                bH[nt][1] = *(const uint32_t*)(p + 8);
                const unsigned short* q = &Blo[n0 * SROW + k0 + lm2];
                bL[nt][0] = *(const uint32_t*)q;
                bL[nt][1] = *(const uint32_t*)(q + 8);
            }
#pragma unroll
            for (int mt = 0; mt < 4; ++mt)
#pragma unroll
                for (int nt = 0; nt < 4; ++nt) {
                    mma16816(d[mt * 4 + nt], aH[mt], bH[nt]);
                    mma16816(d[mt * 4 + nt], aL[mt], bH[nt]);
                    mma16816(d[mt * 4 + nt], aH[mt], bL[nt]);
                }
        }
        __syncthreads();
    }

    size_t gb = (size_t)b * GSTRIDE;
#pragma unroll
    for (int mt = 0; mt < 4; ++mt) {
#pragma unroll
        for (int nt = 0; nt < 4; ++nt) {
            int i0 = ti * 128 + warp_m * 64 + mt * 16 + l4;
            int j0 = tj * 128 + warp_n * 32 + nt * 8 + lm2;
            float* dst0 = &g_G[gb + (size_t)i0 * 258 + j0];
            float* dst1 = &g_G[gb + (size_t)(i0 + 8) * 258 + j0];
            *(float2*)dst0 = make_float2(d[mt * 4 + nt][0], d[mt * 4 + nt][1]);
            *(float2*)dst1 = make_float2(d[mt * 4 + nt][2], d[mt * 4 + nt][3]);
        }
    }
}

// ---------------------------------------------------------------------------
// Phase C: blocked Cholesky (NB=32), panel staged into rectangular P for
// conflict-free SYRK. One CTA per batch, 256 threads, full register budget.
// smem: T packed (33153) + y (257) + P (225*33 = 7425) floats.
// ---------------------------------------------------------------------------
#define TRI(i) ((i) * ((i) + 1) / 2)
#define PSTR 33

__global__ void __launch_bounds__(256, 1) solve_kernel(float* __restrict__ out)
{
    extern __shared__ float sm[];
    float* T = sm;
    float* y = sm + 33153;
    float* P = sm + 33410;
    int b = blockIdx.x;
    int tid = threadIdx.x;
    size_t gb = (size_t)b * GSTRIDE;

    for (int idx = tid; idx < 33153; idx += 256) {
        int i = (int)((sqrtf(8.f * idx + 1.f) - 1.f) * 0.5f);
        while (TRI(i + 1) <= idx) ++i;
        while (TRI(i) > idx) --i;
        int j = idx - TRI(i);
        float v = g_G[gb + (size_t)i * 258 + j];
        if (i == j) v += 25.f;
        T[idx] = v;
    }
    for (int j = tid; j < 257; j += 256) y[j] = g_G[gb + (size_t)257 * 258 + j];
    __syncthreads();

    for (int kb = 0; kb < 256; kb += 32) {
        // --- 1) factor 32x32 diagonal block (warp 0) ---
        if (tid < 32) {
            for (int c = 0; c < 32; ++c) {
                int crow = TRI(kb + c) + kb;
                float dsq = T[crow + c];
                __syncwarp();
                float dv = sqrtf(dsq);
                if (tid == c) T[crow + c] = dv;
                float lr = 0.f;
                int rrow = TRI(kb + tid) + kb;
                if (tid > c) {
                    lr = T[rrow + c] / dv;
                    T[rrow + c] = lr;
                }
                __syncwarp();
                if (tid > c) {
                    for (int c2 = c + 1; c2 <= tid; ++c2)
                        T[rrow + c2] -= lr * T[TRI(kb + c2) + kb + c];
                }
                __syncwarp();
            }
        }
        __syncthreads();

        int base = kb + 32;
        int R = 257 - base;

        // --- 2) panel solve: rows i in [base, 257); stage into P[r][PSTR] ---
        {
            int i = base + tid;
            if (tid < R) {
                int ibase = TRI(i) + kb;
                float row[32];
#pragma unroll
                for (int m = 0; m < 32; ++m) row[m] = T[ibase + m];
#pragma unroll
                for (int c = 0; c < 32; ++c) {
                    int lb = TRI(kb + c) + kb;
                    float v = row[c];
#pragma unroll
                    for (int m = 0; m < c; ++m) v -= row[m] * T[lb + m];
                    row[c] = v / T[lb + c];
                }
#pragma unroll
                for (int m = 0; m < 32; ++m) {
                    T[ibase + m] = row[m];
                    P[tid * PSTR + m] = row[m];
                }
            }
        }
        __syncthreads();

        // --- 3) trailing SYRK: A22 -= L21 L21^T, operands from P ---
        {
            int Gg = (R + 3) >> 2;
            int nt = Gg * (Gg + 1) / 2;
            for (int tIdx = tid; tIdx < nt; tIdx += 256) {
                int gi = (int)((sqrtf(8.f * tIdx + 1.f) - 1.f) * 0.5f);
                while (TRI(gi + 1) <= tIdx) ++gi;
                while (TRI(gi) > tIdx) --gi;
                int gj = tIdx - TRI(gi);
                int pi[4], pj[4];
#pragma unroll
                for (int q = 0; q < 4; ++q) {
                    int iq = gi * 4 + q; if (iq > R - 1) iq = R - 1;
                    int jq = gj * 4 + q; if (jq > R - 1) jq = R - 1;
                    pi[q] = iq * PSTR;
                    pj[q] = jq * PSTR;
                }
                unsigned long long acc[4][2];
#pragma unroll
                for (int q = 0; q < 4; ++q) { acc[q][0] = 0ull; acc[q][1] = 0ull; }
#pragma unroll 8
                for (int m = 0; m < 32; ++m) {
                    unsigned long long pb01 = pack2(P[pj[0] + m], P[pj[1] + m]);
                    unsigned long long pb23 = pack2(P[pj[2] + m], P[pj[3] + m]);
#pragma unroll
                    for (int q = 0; q < 4; ++q) {
                        unsigned long long a2 = splat2(P[pi[q] + m]);
                        fma2(acc[q][0], a2, pb01);
                        fma2(acc[q][1], a2, pb23);
                    }
                }
                int i0 = base + gi * 4, j0 = base + gj * 4;
#pragma unroll
                for (int q = 0; q < 4; ++q) {
                    int i = i0 + q;
                    if (i > 256) continue;
                    float2 v0 = unpk(acc[q][0]);
                    float2 v1 = unpk(acc[q][1]);
                    int tb = TRI(i);
                    if (j0     <= i            ) T[tb + j0]     -= v0.x;
                    if (j0 + 1 <= i && j0+1<257) T[tb + j0 + 1] -= v0.y;
                    if (j0 + 2 <= i && j0+2<257) T[tb + j0 + 2] -= v1.x;
                    if (j0 + 3 <= i && j0+3<257) T[tb + j0 + 3] -= v1.y;
                }
            }
        }
        __syncthreads();
    }
    if (tid == 0) T[TRI(256) + 256] = sqrtf(T[TRI(256) + 256]);
    __syncthreads();

    // substitutions in warp 0: L y = rhs, then L^T x = y
    if (tid < 32) {
        for (int k = 0; k < 257; ++k) {
            float num = y[k];
            float dg = T[TRI(k) + k];
            __syncwarp();
            float yk = num / dg;
            if (tid == 0) y[k] = yk;
            for (int i = k + 1 + tid; i < 257; i += 32)
                y[i] -= T[TRI(i) + k] * yk;
            __syncwarp();
        }
        for (int k = 256; k >= 0; --k) {
            float num = y[k];
            float dg = T[TRI(k) + k];
            __syncwarp();
            float xk = num / dg;
            if (tid == 0) y[k] = xk;
            int rb = TRI(k);
            for (int i = tid; i < k; i += 32)
                y[i] -= T[rb + i] * xk;
            __syncwarp();
        }
    }
    __syncthreads();
    for (int j = tid; j < 257; j += 256) out[b * 257 + j] = y[j];
}

// ---------------------------------------------------------------------------
extern "C" void kernel_launch(void* const* d_in, const int* in_sizes, int n_in,
                              void* d_out, int out_size)
{
    (void)in_sizes; (void)n_in; (void)out_size;
    const float* img = (const float*)d_in[0];
    const float* win = (const float*)d_in[1];
    const float* W1  = (const float*)d_in[2];
    const float* W2  = (const float*)d_in[3];
    float* out = (float*)d_out;

    int solve_smem = (33153 + 257 + 225 * PSTR) * (int)sizeof(float);
    cudaFuncSetAttribute(solve_kernel, cudaFuncAttributeMaxDynamicSharedMemorySize,
                         solve_smem);
    int gram_smem = 4 * 128 * SROW * 2;  // 73728 bytes
    cudaFuncSetAttribute(gram_mma, cudaFuncAttributeMaxDynamicSharedMemorySize, gram_smem);

    esn_persist<<<128, 256>>>(img, win, W1, W2);
    feat_kernel<<<256, 256>>>(img);
    gram_mma<<<dim3(3, 256), 256, gram_smem>>>();
    solve_kernel<<<256, 256, solve_smem>>>(out);
}

// round 7
// speedup vs baseline: 2.1762x; 1.3064x over previous
#include <cuda_runtime.h>
#include <cuda_bf16.h>
#include <cstdint>

// ---------------------------------------------------------------------------
// ESN_2D: B=256, H=W=32, n=128, alpha^2=25, START_T=1
//  Phase A: persistent per-batch-pair wavefront kernel
//  Phase B: feat (bf16 hi/lo features) + mma.sync bf16-split Gram
//  Phase C: out-of-smem blocked Cholesky (trailing matrix in global, panel in
//           smem, 2 CTAs/SM, single wave) + blocked substitutions
// ---------------------------------------------------------------------------

#define GSTRIDE 66564  // 258*258

__device__ float g_S[(size_t)1024 * 256 * 128];
__device__ float g_G[(size_t)256 * GSTRIDE];
__device__ unsigned short g_Fhi[(size_t)256 * 256 * 1024];
__device__ unsigned short g_Flo[(size_t)256 * 256 * 1024];

// ---- packed f32x2 helpers ----
__device__ __forceinline__ unsigned long long splat2(float x) {
    unsigned long long r;
    asm("mov.b64 %0, {%1, %1};" : "=l"(r) : "f"(x));
    return r;
}
__device__ __forceinline__ void fma2(unsigned long long &c, unsigned long long a,
                                     unsigned long long b) {
    asm("fma.rn.f32x2 %0, %1, %2, %0;" : "+l"(c) : "l"(a), "l"(b));
}
__device__ __forceinline__ float2 unpk(unsigned long long v) {
    float2 f;
    asm("mov.b64 {%0, %1}, %2;" : "=f"(f.x), "=f"(f.y) : "l"(v));
    return f;
}

// ---- cp.async helpers ----
__device__ __forceinline__ uint32_t smem_u32(const void* p) {
    uint32_t a;
    asm("{ .reg .u64 t; cvta.to.shared.u64 t, %1; cvt.u32.u64 %0, t; }" : "=r"(a) : "l"(p));
    return a;
}
__device__ __forceinline__ void cpasync16(uint32_t dst, const void* src) {
    asm volatile("cp.async.cg.shared.global [%0], [%1], 16;" :: "r"(dst), "l"(src) : "memory");
}
__device__ __forceinline__ void cpasync_commit() {
    asm volatile("cp.async.commit_group;" ::: "memory");
}
__device__ __forceinline__ void cpasync_wait0() {
    asm volatile("cp.async.wait_group 0;" ::: "memory");
}

// ---- bf16 mma.sync ----
__device__ __forceinline__ void mma16816(float* d, const uint32_t* a, const uint32_t* b) {
    asm volatile(
        "mma.sync.aligned.m16n8k16.row.col.f32.bf16.bf16.f32 "
        "{%0,%1,%2,%3}, {%4,%5,%6,%7}, {%8,%9}, {%0,%1,%2,%3};"
        : "+f"(d[0]), "+f"(d[1]), "+f"(d[2]), "+f"(d[3])
        : "r"(a[0]), "r"(a[1]), "r"(a[2]), "r"(a[3]), "r"(b[0]), "r"(b[1]));
}

// ---------------------------------------------------------------------------
// Phase A: persistent recurrence. grid=128 CTAs (2 batches each), 256 threads.
// ---------------------------------------------------------------------------
__global__ void __launch_bounds__(256) esn_persist(const float* __restrict__ img,
                                                   const float* __restrict__ win,
                                                   const float* __restrict__ W1,
                                                   const float* __restrict__ W2)
{
    int b0 = blockIdx.x * 2;
    int t = threadIdx.x;
    int ip = t & 63;
    int jg = t >> 6;

    unsigned long long w1r[32], w2r[32];
#pragma unroll
    for (int m = 0; m < 32; ++m) {
        int j = jg * 32 + m;
        w1r[m] = *(const unsigned long long*)&W1[j * 128 + ip * 2];
        w2r[m] = *(const unsigned long long*)&W2[j * 128 + ip * 2];
    }

    __shared__ float rowbuf[2][32][128];
    __shared__ float lbuf[2][128];
    __shared__ float red[4][2][128];

    for (int idx = t; idx < 2 * 32 * 128; idx += 256)
        ((float*)rowbuf)[idx] = 0.f;

    int rg = t >> 7;
    int ri = t & 127;
    float winv = win[ri];

    for (int h = 0; h < 32; ++h) {
        lbuf[rg][ri] = 0.f;
        __syncthreads();
        for (int w = 0; w < 32; ++w) {
            int cell = h * 32 + w;
#pragma unroll
            for (int g = 0; g < 2; ++g) {
                unsigned long long accA = 0ull, accB = 0ull;
                const float* lb = &lbuf[g][jg * 32];
                const float* ub = &rowbuf[g][w][jg * 32];
#pragma unroll
                for (int m4 = 0; m4 < 8; ++m4) {
                    float4 lv = *(const float4*)&lb[m4 * 4];
                    float4 uv = *(const float4*)&ub[m4 * 4];
                    fma2(accA, splat2(lv.x), w1r[m4 * 4 + 0]);
                    fma2(accB, splat2(uv.x), w2r[m4 * 4 + 0]);
                    fma2(accA, splat2(lv.y), w1r[m4 * 4 + 1]);
                    fma2(accB, splat2(uv.y), w2r[m4 * 4 + 1]);
                    fma2(accA, splat2(lv.z), w1r[m4 * 4 + 2]);
                    fma2(accB, splat2(uv.z), w2r[m4 * 4 + 2]);
                    fma2(accA, splat2(lv.w), w1r[m4 * 4 + 3]);
                    fma2(accB, splat2(uv.w), w2r[m4 * 4 + 3]);
                }
                float2 a = unpk(accA), bb = unpk(accB);
                *(float2*)&red[jg][g][ip * 2] = make_float2(a.x + bb.x, a.y + bb.y);
            }
            __syncthreads();
            {
                float s = (red[0][rg][ri] + red[1][rg][ri]) +
                          (red[2][rg][ri] + red[3][rg][ri]);
                float x = img[(b0 + rg) * 1024 + cell];
                float v = tanhf(fmaf(x, winv, s));
                lbuf[rg][ri] = v;
                rowbuf[rg][w][ri] = v;
                g_S[(size_t)cell * 32768 + (size_t)(b0 + rg) * 128 + ri] = v;
            }
            __syncthreads();
        }
    }
}

// ---------------------------------------------------------------------------
// feat kernel
// ---------------------------------------------------------------------------
__global__ void __launch_bounds__(256) feat_kernel(const float* __restrict__ img)
{
    int b = blockIdx.x;
    int d = threadIdx.x;
    bool isLeft = d < 128;
    int dd = d & 127;

    float sumF = 0.f, sumUF = 0.f, su = 0.f;
    int hh = 0, ww = 0;

    uint4* outHi = (uint4*)&g_Fhi[((size_t)b * 256 + d) * 1024];
    uint4* outLo = (uint4*)&g_Flo[((size_t)b * 256 + d) * 1024];

    for (int sg = 0; sg < 128; ++sg) {
        unsigned short h8[8], l8[8];
#pragma unroll
        for (int j = 0; j < 8; ++j) {
            int s = sg * 8 + j;
            float f = 0.f, u = 0.f;
            if (s < 961) {
                int cell_l = (hh + 1) * 32 + ww;
                int cell_u = hh * 32 + ww + 1;
                int cell_t = (hh + 1) * 32 + ww + 1;
                int cell = isLeft ? cell_l : cell_u;
                f = g_S[(size_t)cell * 32768 + (size_t)b * 128 + dd];
                u = img[b * 1024 + cell_t];
                ++ww;
                if (ww == 31) { ww = 0; ++hh; }
            }
            __nv_bfloat16 hi = __float2bfloat16_rn(f);
            float hif = __bfloat162float(hi);
            __nv_bfloat16 lo = __float2bfloat16_rn(f - hif);
            h8[j] = __bfloat16_as_ushort(hi);
            l8[j] = __bfloat16_as_ushort(lo);
            sumF += f;
            sumUF += u * f;
            su += u;
        }
        uint4 vh, vl;
        vh.x = (uint32_t)h8[0] | ((uint32_t)h8[1] << 16);
        vh.y = (uint32_t)h8[2] | ((uint32_t)h8[3] << 16);
        vh.z = (uint32_t)h8[4] | ((uint32_t)h8[5] << 16);
        vh.w = (uint32_t)h8[6] | ((uint32_t)h8[7] << 16);
        vl.x = (uint32_t)l8[0] | ((uint32_t)l8[1] << 16);
        vl.y = (uint32_t)l8[2] | ((uint32_t)l8[3] << 16);
        vl.z = (uint32_t)l8[4] | ((uint32_t)l8[5] << 16);
        vl.w = (uint32_t)l8[6] | ((uint32_t)l8[7] << 16);
        outHi[sg] = vh;
        outLo[sg] = vl;
    }

    size_t gb = (size_t)b * GSTRIDE;
    g_G[gb + (size_t)256 * 258 + d] = sumF;
    g_G[gb + (size_t)257 * 258 + d] = sumUF;
    if (d == 0) {
        g_G[gb + (size_t)256 * 258 + 256] = 961.f;
        g_G[gb + (size_t)257 * 258 + 256] = su;
    }
}

// ---------------------------------------------------------------------------
// gram_mma (unchanged passing version)
// ---------------------------------------------------------------------------
#define SROW 72

__global__ void __launch_bounds__(256) gram_mma()
{
    extern __shared__ unsigned short sh[];
    int tile = blockIdx.x;
    int b = blockIdx.y;
    int ti = (tile > 0) ? 1 : 0;
    int tj = (tile == 2) ? 1 : 0;
    bool diag = (ti == tj);

    int tid = threadIdx.x;
    int lane = tid & 31;
    int wq = tid >> 5;
    int warp_m = wq >> 2;
    int warp_n = wq & 3;
    int l4 = lane >> 2;
    int lm2 = (lane & 3) * 2;

    unsigned short* Ahi = sh;
    unsigned short* Alo = sh + 128 * SROW;
    unsigned short* Bhi = diag ? Ahi : sh + 2 * 128 * SROW;
    unsigned short* Blo = diag ? Alo : sh + 3 * 128 * SROW;

    uint32_t uAhi = smem_u32(Ahi);
    uint32_t uAlo = smem_u32(Alo);
    uint32_t uBhi = smem_u32(Bhi);
    uint32_t uBlo = smem_u32(Blo);

    const unsigned short* srcAhi = &g_Fhi[((size_t)b * 256 + ti * 128) * 1024];
    const unsigned short* srcAlo = &g_Flo[((size_t)b * 256 + ti * 128) * 1024];
    const unsigned short* srcBhi = &g_Fhi[((size_t)b * 256 + tj * 128) * 1024];
    const unsigned short* srcBlo = &g_Flo[((size_t)b * 256 + tj * 128) * 1024];

    float d[16][4];
#pragma unroll
    for (int q = 0; q < 16; ++q)
#pragma unroll
        for (int r = 0; r < 4; ++r) d[q][r] = 0.f;

    for (int c = 0; c < 16; ++c) {
        int s0 = c * 64;
#pragma unroll
        for (int q = 0; q < 4; ++q) {
            int idx = tid + q * 256;
            int r = idx >> 3, cc = idx & 7;
            uint32_t dsto = (uint32_t)(r * SROW * 2 + cc * 16);
            size_t srco = (size_t)r * 1024 + s0 + cc * 8;
            cpasync16(uAhi + dsto, srcAhi + srco);
            cpasync16(uAlo + dsto, srcAlo + srco);
            if (!diag) {
                cpasync16(uBhi + dsto, srcBhi + srco);
                cpasync16(uBlo + dsto, srcBlo + srco);
            }
        }
        cpasync_commit();
        cpasync_wait0();
        __syncthreads();

#pragma unroll
        for (int ks = 0; ks < 4; ++ks) {
            int k0 = ks * 16;
            uint32_t aH[4][4], aL[4][4], bH[4][2], bL[4][2];
#pragma unroll
            for (int mt = 0; mt < 4; ++mt) {
                int r0 = warp_m * 64 + mt * 16 + l4;
                const unsigned short* p0 = &Ahi[r0 * SROW + k0 + lm2];
                const unsigned short* p1 = &Ahi[(r0 + 8) * SROW + k0 + lm2];
                aH[mt][0] = *(const uint32_t*)p0;
                aH[mt][1] = *(const uint32_t*)p1;
                aH[mt][2] = *(const uint32_t*)(p0 + 8);
                aH[mt][3] = *(const uint32_t*)(p1 + 8);
                const unsigned short* q0 = &Alo[r0 * SROW + k0 + lm2];
                const unsigned short* q1 = &Alo[(r0 + 8) * SROW + k0 + lm2];
                aL[mt][0] = *(const uint32_t*)q0;
                aL[mt][1] = *(const uint32_t*)q1;
                aL[mt][2] = *(const uint32_t*)(q0 + 8);
                aL[mt][3] = *(const uint32_t*)(q1 + 8);
            }
#pragma unroll
            for (int nt = 0; nt < 4; ++nt) {
                int n0 = warp_n * 32 + nt * 8 + l4;
                const unsigned short* p = &Bhi[n0 * SROW + k0 + lm2];
                bH[nt][0] = *(const uint32_t*)p;
                bH[nt][1] = *(const uint32_t*)(p + 8);
                const unsigned short* q = &Blo[n0 * SROW + k0 + lm2];
                bL[nt][0] = *(const uint32_t*)q;
                bL[nt][1] = *(const uint32_t*)(q + 8);
            }
#pragma unroll
            for (int mt = 0; mt < 4; ++mt)
#pragma unroll
                for (int nt = 0; nt < 4; ++nt) {
                    mma16816(d[mt * 4 + nt], aH[mt], bH[nt]);
                    mma16816(d[mt * 4 + nt], aL[mt], bH[nt]);
                    mma16816(d[mt * 4 + nt], aH[mt], bL[nt]);
                }
        }
        __syncthreads();
    }

    size_t gb = (size_t)b * GSTRIDE;
#pragma unroll
    for (int mt = 0; mt < 4; ++mt) {
#pragma unroll
        for (int nt = 0; nt < 4; ++nt) {
            int i0 = ti * 128 + warp_m * 64 + mt * 16 + l4;
            int j0 = tj * 128 + warp_n * 32 + nt * 8 + lm2;
            float* dst0 = &g_G[gb + (size_t)i0 * 258 + j0];
            float* dst1 = &g_G[gb + (size_t)(i0 + 8) * 258 + j0];
            *(float2*)dst0 = make_float2(d[mt * 4 + nt][0], d[mt * 4 + nt][1]);
            *(float2*)dst1 = make_float2(d[mt * 4 + nt][2], d[mt * 4 + nt][3]);
        }
    }
}

// ---------------------------------------------------------------------------
// Phase C: out-of-smem blocked Cholesky (trailing matrix in g_G) + blocked
// substitutions. smem ~67KB -> 2 CTAs/SM, 1 wave.
// ---------------------------------------------------------------------------
#define TRI(i) ((i) * ((i) + 1) / 2)
#define PTS 264
#define BRS 260

__global__ void __launch_bounds__(256, 2) solve_kernel(float* __restrict__ out)
{
    extern __shared__ float sm[];
    float* pan = sm;              // 8484 (row stride 33, indexed by abs row)
    float* Pt  = sm + 8484;       // 8448 (16B-aligned rows, stride 264)
    float* y   = sm + 16932;      // 260
    int b = blockIdx.x;
    int tid = threadIdx.x;
    float* A = &g_G[(size_t)b * GSTRIDE];

    for (int j = tid; j < 257; j += 256) y[j] = A[(size_t)257 * 258 + j];

    // ---------------- factorization ----------------
    for (int kb = 0; kb < 256; kb += 32) {
        int Rf = 257 - kb;
        // 1) stage panel (+ alpha^2 on diag)
        for (int idx = tid; idx < Rf * 32; idx += 256) {
            int r = idx >> 5, c = idx & 31;
            float v = A[(size_t)(kb + r) * 258 + kb + c];
            if (r == c) v += 25.f;
            pan[(kb + r) * 33 + c] = v;
        }
        __syncthreads();
        // 2) factor 32x32 diag block (warp 0)
        if (tid < 32) {
            for (int c = 0; c < 32; ++c) {
                float dsq = pan[(kb + c) * 33 + c];
                __syncwarp();
                float dv = sqrtf(dsq);
                if (tid == c) pan[(kb + c) * 33 + c] = dv;
                float lr = 0.f;
                if (tid > c) {
                    lr = pan[(kb + tid) * 33 + c] / dv;
                    pan[(kb + tid) * 33 + c] = lr;
                }
                __syncwarp();
                if (tid > c)
                    for (int c2 = c + 1; c2 <= tid; ++c2)
                        pan[(kb + tid) * 33 + c2] -= lr * pan[(kb + c2) * 33 + c];
                __syncwarp();
            }
        }
        __syncthreads();
        int base = kb + 32;
        int R = 257 - base;
        // 3) panel triangular solve; results to pan + transposed Pt
        if (tid < R) {
            int i = base + tid;
            float row[32];
#pragma unroll
            for (int m = 0; m < 32; ++m) row[m] = pan[i * 33 + m];
#pragma unroll
            for (int c = 0; c < 32; ++c) {
                float v = row[c];
#pragma unroll
                for (int m = 0; m < c; ++m) v -= row[m] * pan[(kb + c) * 33 + m];
                row[c] = v / pan[(kb + c) * 33 + c];
            }
#pragma unroll
            for (int m = 0; m < 32; ++m) {
                pan[i * 33 + m] = row[m];
                Pt[m * PTS + tid] = row[m];
            }
        }
        __syncthreads();
        // 4) coalesced writeback of L panel (rows kb..256)
        for (int idx = tid; idx < Rf * 32; idx += 256) {
            int r = idx >> 5, c = idx & 31;
            A[(size_t)(kb + r) * 258 + kb + c] = pan[(kb + r) * 33 + c];
        }
        // 5) trailing SYRK, RMW in global (4x4 reg tiles from Pt)
        if (R > 0) {
            int Gg = (R + 3) >> 2;
            int nt = Gg * (Gg + 1) / 2;
            for (int tIdx = tid; tIdx < nt; tIdx += 256) {
                int gi = (int)((sqrtf(8.f * tIdx + 1.f) - 1.f) * 0.5f);
                while (TRI(gi + 1) <= tIdx) ++gi;
                while (TRI(gi) > tIdx) --gi;
                int gj = tIdx - TRI(gi);
                int i0 = base + gi * 4, j0 = base + gj * 4;
                unsigned long long acc[4][2];
#pragma unroll
                for (int q = 0; q < 4; ++q) { acc[q][0] = 0ull; acc[q][1] = 0ull; }
#pragma unroll 8
                for (int m = 0; m < 32; ++m) {
                    float4 av = *(const float4*)&Pt[m * PTS + gi * 4];
                    ulonglong2 bv = *(const ulonglong2*)&Pt[m * PTS + gj * 4];
                    unsigned long long s;
                    s = splat2(av.x); fma2(acc[0][0], s, bv.x); fma2(acc[0][1], s, bv.y);
                    s = splat2(av.y); fma2(acc[1][0], s, bv.x); fma2(acc[1][1], s, bv.y);
                    s = splat2(av.z); fma2(acc[2][0], s, bv.x); fma2(acc[2][1], s, bv.y);
                    s = splat2(av.w); fma2(acc[3][0], s, bv.x); fma2(acc[3][1], s, bv.y);
                }
                if (i0 + 3 <= 256 && j0 + 3 <= 256) {
#pragma unroll
                    for (int q = 0; q < 4; ++q) {
                        float* ap = &A[(size_t)(i0 + q) * 258 + j0];
                        float2 o0 = *(float2*)ap;
                        float2 o1 = *(float2*)(ap + 2);
                        float2 v0 = unpk(acc[q][0]);
                        float2 v1 = unpk(acc[q][1]);
                        o0.x -= v0.x; o0.y -= v0.y;
                        o1.x -= v1.x; o1.y -= v1.y;
                        *(float2*)ap = o0;
                        *(float2*)(ap + 2) = o1;
                    }
                } else {
#pragma unroll
                    for (int q = 0; q < 4; ++q) {
                        int i = i0 + q;
                        if (i > 256) continue;
                        float2 v0 = unpk(acc[q][0]);
                        float2 v1 = unpk(acc[q][1]);
                        float vv[4] = {v0.x, v0.y, v1.x, v1.y};
#pragma unroll
                        for (int p = 0; p < 4; ++p) {
                            int j = j0 + p;
                            if (j > 256) continue;
                            A[(size_t)i * 258 + j] -= vv[p];
                        }
                    }
                }
            }
        }
        __syncthreads();
    }
    // final corner element (row 256 never owned a diag block)
    if (tid == 0)
        A[(size_t)256 * 258 + 256] = sqrtf(A[(size_t)256 * 258 + 256] + 25.f);
    __syncthreads();

    // ---------------- forward substitution: L y = rhs ----------------
    for (int kb = 0; kb < 256; kb += 32) {
        int Rf = 257 - kb;
        for (int idx = tid; idx < Rf * 32; idx += 256) {
            int r = idx >> 5, c = idx & 31;
            pan[(kb + r) * 33 + c] = A[(size_t)(kb + r) * 258 + kb + c];
        }
        __syncthreads();
        if (tid < 32) {
            float acc = y[kb + tid];
#pragma unroll
            for (int m = 0; m < 32; ++m) {
                float dm = pan[(kb + m) * 33 + m];
                if (tid == m) acc /= dm;
                float ym = __shfl_sync(0xffffffffu, acc, m);
                if (tid > m) acc -= pan[(kb + tid) * 33 + m] * ym;
            }
            y[kb + tid] = acc;
        }
        __syncthreads();
        int R = 225 - kb;
        if (tid < R) {
            int i = kb + 32 + tid;
            float acc = y[i];
#pragma unroll
            for (int c = 0; c < 32; ++c) acc -= pan[i * 33 + c] * y[kb + c];
            y[i] = acc;
        }
        __syncthreads();
    }
    if (tid == 0) y[256] /= A[(size_t)256 * 258 + 256];
    __syncthreads();

    // ---------------- backward substitution: L^T x = y ----------------
    // x[256] = y[256] / L[256][256]  (second division for the transpose solve)
    if (tid == 0) y[256] /= A[(size_t)256 * 258 + 256];
    __syncthreads();
    {
        float x256 = y[256];
        if (tid < 256) y[tid] -= A[(size_t)256 * 258 + tid] * x256;
        __syncthreads();
    }
    for (int kb = 224; kb >= 0; kb -= 32) {
        // stage rows kb..kb+31, cols 0..255 (stride BRS)
        for (int idx = tid; idx < 32 * 256; idx += 256) {
            int c = idx >> 8, j = idx & 255;
            pan[c * BRS + j] = A[(size_t)(kb + c) * 258 + j];
        }
        __syncthreads();
        if (tid < 32) {
            float acc = y[kb + tid];
#pragma unroll
            for (int m = 31; m >= 0; --m) {
                float dm = pan[m * BRS + kb + m];
                if (tid == m) acc /= dm;
                float ym = __shfl_sync(0xffffffffu, acc, m);
                if (tid < m) acc -= pan[m * BRS + kb + tid] * ym;
            }
            y[kb + tid] = acc;
        }
        __syncthreads();
        if (tid < kb) {
            float acc = y[tid];
#pragma unroll
            for (int c = 0; c < 32; ++c) acc -= pan[c * BRS + tid] * y[kb + c];
            y[tid] = acc;
        }
        __syncthreads();
    }
    for (int j = tid; j < 257; j += 256) out[b * 257 + j] = y[j];
}

// ---------------------------------------------------------------------------
extern "C" void kernel_launch(void* const* d_in, const int* in_sizes, int n_in,
                              void* d_out, int out_size)
{
    (void)in_sizes; (void)n_in; (void)out_size;
    const float* img = (const float*)d_in[0];
    const float* win = (const float*)d_in[1];
    const float* W1  = (const float*)d_in[2];
    const float* W2  = (const float*)d_in[3];
    float* out = (float*)d_out;

    int solve_smem = 17192 * (int)sizeof(float);  // 68768 B -> 2 CTAs/SM
    cudaFuncSetAttribute(solve_kernel, cudaFuncAttributeMaxDynamicSharedMemorySize,
                         solve_smem);
    int gram_smem = 4 * 128 * SROW * 2;  // 73728 B
    cudaFuncSetAttribute(gram_mma, cudaFuncAttributeMaxDynamicSharedMemorySize, gram_smem);

    esn_persist<<<128, 256>>>(img, win, W1, W2);
    feat_kernel<<<256, 256>>>(img);
    gram_mma<<<dim3(3, 256), 256, gram_smem>>>();
    solve_kernel<<<256, 256, solve_smem>>>(out);
}